// round 12
// baseline (speedup 1.0000x reference)
#include <cuda_runtime.h>
#include <cuda_bf16.h>
#include <cstdint>

#define THREADS 256
#define NB 4                          // batches per CTA -> 64 t-columns
#define LDP 72                        // padded smem row stride (floats)

// ---------------- smem byte layout ----------------
#define SM_XS 0                              // X : 40 x 72 f32 = 11520
#define SM_PS (40*LDP*4)                     // P : 64 x 72 f32 = 18432
#define SM_W0 (SM_PS + 64*LDP*4)             // W chunk32 buf0 (16KB)
#define SM_W1 (SM_W0 + 16384)                // W chunk32 buf1 (16KB)
#define SMEM_BYTES (SM_W1 + 16384)           // 62,720 bytes -> 3 CTAs/SM

// ---------------- prepped-W global scratch ----------------
// K=32 chunks. Per chunk: [s2=0|1 k16-step] x [tile-pairs] x [hi|lo] blocks.
// Block = 32 lanes x 16B: per lane {tile2p.b0, tile2p.b1, tile2p+1.b0, tile2p+1.b1}
#define NT0 16
#define NT1 16
#define NT2 8
#define CH0 50
#define CH1 80
#define CH2 80
#define CHB0 (NT0*1024)      // 16384 B per chunk32
#define CHB1 (NT1*1024)      // 16384 B
#define CHB2 (NT2*1024)      // 8192 B
#define OFF0 0u
#define OFF1 (CH0*CHB0)                  // 819200
#define OFF2 (OFF1 + CH1*CHB1)           // 2129920
#define WPRE_BYTES (OFF2 + CH2*CHB2)     // 2785280

__device__ __align__(16) uint8_t g_wpre[WPRE_BYTES];

// ---------------- helpers ----------------
__device__ __forceinline__ uint32_t packb(float lo, float hi) {
    uint32_t r;
    asm("cvt.rn.bf16x2.f32 %0, %1, %2;" : "=r"(r) : "f"(hi), "f"(lo));
    return r;
}
__device__ __forceinline__ uint32_t prmt_hi(float a, float b) {
    uint32_t r;
    asm("prmt.b32 %0, %1, %2, 0x7632;"
        : "=r"(r) : "r"(__float_as_uint(a)), "r"(__float_as_uint(b)));
    return r;
}
__device__ __forceinline__ float trunc_hi(float v) {
    return __uint_as_float(__float_as_uint(v) & 0xFFFF0000u);
}
__device__ __forceinline__ void mma_bf16(float* c, const uint32_t* a,
                                         uint32_t b0, uint32_t b1) {
    asm volatile(
        "mma.sync.aligned.m16n8k16.row.col.f32.bf16.bf16.f32 "
        "{%0,%1,%2,%3}, {%4,%5,%6,%7}, {%8,%9}, {%0,%1,%2,%3};"
        : "+f"(c[0]), "+f"(c[1]), "+f"(c[2]), "+f"(c[3])
        : "r"(a[0]), "r"(a[1]), "r"(a[2]), "r"(a[3]), "r"(b0), "r"(b1));
}
__device__ __forceinline__ uint32_t smem_u32(const void* p) {
    uint32_t a;
    asm("{ .reg .u64 t; cvta.to.shared.u64 t, %1; cvt.u32.u64 %0, t; }" : "=r"(a) : "l"(p));
    return a;
}
__device__ __forceinline__ void cp_async16(uint32_t dst, const void* src) {
    asm volatile("cp.async.cg.shared.global [%0], [%1], 16;" :: "r"(dst), "l"(src));
}
#define CP_COMMIT() asm volatile("cp.async.commit_group;" ::: "memory")
#define CP_WAIT0()  asm volatile("cp.async.wait_group 0;" ::: "memory")

// ---------------- prep: truncation-split W into paired B-fragment blocks ----------------
#define WORDS0 (CH0*NT0*256)   // 204800
#define WORDS1 (CH1*NT1*256)   // 327680
#define WORDS2 (CH2*NT2*256)   // 163840

__global__ void prep_kernel(const float* __restrict__ w0,
                            const float* __restrict__ w1,
                            const float* __restrict__ w2)
{
    int i = blockIdx.x * blockDim.x + threadIdx.x;
    if (i >= WORDS0 + WORDS1 + WORDS2) return;
    const float* src; int NT, ld, rowBase, li; uint32_t off, chb;
    if (i < WORDS0)               { src=w0; NT=NT0; ld=1600; rowBase=0;  off=OFF0; chb=CHB0; li=i; }
    else if (i < WORDS0+WORDS1)   { src=w1; NT=NT1; ld=2560; rowBase=0;  off=OFF1; chb=CHB1; li=i-WORDS0; }
    else                          { src=w2; NT=NT2; ld=2560; rowBase=64; off=OFF2; chb=CHB2; li=i-WORDS0-WORDS1; }

    int perChunk = NT * 256;                  // b32 words per chunk32
    int c    = li / perChunk;
    int r    = li - c * perChunk;
    int half = NT * 128;                      // words per k16-step
    int s2   = r / half;
    int r2   = r - s2 * half;
    int pair = r2 >> 8;                       // / 256
    int r3   = r2 & 255;
    int sel  = r3 >> 7;                       // 0=hi, 1=lo
    int r4   = r3 & 127;
    int lane = r4 >> 2;
    int w4   = r4 & 3;                        // word within 16B
    int tile = pair * 2 + (w4 >> 1);
    int wsel = w4 & 1;                        // b0 (k+0..1) or b1 (k+8..9)

    int o = tile * 8 + (lane >> 2);
    int k = c * 32 + s2 * 16 + (lane & 3) * 2 + wsel * 8;
    float a = __ldg(src + (size_t)(rowBase + o) * ld + k);
    float b = __ldg(src + (size_t)(rowBase + o) * ld + k + 1);
    uint32_t w;
    if (sel) w = packb(a - trunc_hi(a), b - trunc_hi(b));   // lo part
    else     w = prmt_hi(a, b);                              // hi part (exact)

    *(uint32_t*)(g_wpre + off + (size_t)c * chb
                 + s2 * (uint32_t)(NT / 2) * 1024 + pair * 1024 + sel * 512
                 + lane * 16 + w4 * 4) = w;
}

// ---------------- A-fragment build for one m-tile (rows tl, tl+8) ----------------
__device__ __forceinline__ void build_A(
    int step, const float* __restrict__ Pp, const float* __restrict__ Xs,
    int q, int tl, uint32_t* ahi, uint32_t* alo)
{
    const int k0 = step * 16 + q * 2;
    float zl[4], zh[4];
    #pragma unroll
    for (int e = 0; e < 4; ++e) {
        int k = k0 + (e & 1) + (e >> 1) * 8;   // {k0, k0+1, k0+8, k0+9}
        int h = k / 40;
        int m = k - h * 40;
        zl[e] = Pp[h * LDP + tl]     * Xs[m * LDP + tl];
        zh[e] = Pp[h * LDP + tl + 8] * Xs[m * LDP + tl + 8];
    }
    ahi[0] = prmt_hi(zl[0], zl[1]);
    ahi[1] = prmt_hi(zh[0], zh[1]);
    ahi[2] = prmt_hi(zl[2], zl[3]);
    ahi[3] = prmt_hi(zh[2], zh[3]);
    alo[0] = packb(zl[0] - trunc_hi(zl[0]), zl[1] - trunc_hi(zl[1]));
    alo[1] = packb(zh[0] - trunc_hi(zh[0]), zh[1] - trunc_hi(zh[1]));
    alo[2] = packb(zl[2] - trunc_hi(zl[2]), zl[3] - trunc_hi(zl[3]));
    alo[3] = packb(zh[2] - trunc_hi(zh[2]), zh[3] - trunc_hi(zh[3]));
}

// ---------------- one CIN layer: warp = (t16 x o-slice), acc = NTW*4 regs ----------------
template<int NTW, int STEPB, int CHB>
__device__ __forceinline__ void run_layer(
    int nch, const uint8_t* __restrict__ wpre,
    const float* __restrict__ Pp, const float* __restrict__ Xs,
    const uint8_t* __restrict__ wb0, const uint8_t* __restrict__ wb1,
    uint32_t wb0u, uint32_t wb1u, int pairBase,
    float (&acc)[NTW][4], int tid, int lane, int q, int tl)
{
    constexpr int NP  = NTW / 2;              // pairs per warp per step
    constexpr int CPT = CHB / 16 / THREADS;   // cp.async16 per thread

    #pragma unroll
    for (int nt = 0; nt < NTW; ++nt)
        #pragma unroll
        for (int j = 0; j < 4; ++j) acc[nt][j] = 0.0f;

    __syncthreads();   // previous layer's buffer reads / P writes complete

    #pragma unroll
    for (int i = 0; i < CPT; ++i) {
        int e = tid + i * THREADS;
        cp_async16(wb0u + e * 16, wpre + e * 16);
    }
    CP_COMMIT();

    #pragma unroll 1
    for (int c = 0; c < nch; ++c) {
        CP_WAIT0();
        __syncthreads();                      // chunk c visible; prev buffer reads done
        if (c + 1 < nch) {
            const uint8_t* src = wpre + (size_t)(c + 1) * CHB;
            uint32_t dst = ((c + 1) & 1) ? wb1u : wb0u;
            #pragma unroll
            for (int i = 0; i < CPT; ++i) {
                int e = tid + i * THREADS;
                cp_async16(dst + e * 16, src + e * 16);
            }
        }
        CP_COMMIT();                          // overlaps with compute below
        const uint8_t* __restrict__ wb = (c & 1) ? wb1 : wb0;

        #pragma unroll
        for (int s2 = 0; s2 < 2; ++s2) {
            uint32_t ahi[4], alo[4];
            build_A(c * 2 + s2, Pp, Xs, q, tl, ahi, alo);

            const uint8_t* __restrict__ wbs = wb + s2 * STEPB + pairBase;

            #pragma unroll
            for (int p = 0; p < NP; ++p) {
                const uint4 bh = *(const uint4*)(wbs + p * 1024 + lane * 16);
                const uint4 bl = *(const uint4*)(wbs + p * 1024 + 512 + lane * 16);
                // per-acc order: hi*bh, lo*bh, hi*bl (bit-identical per D element)
                mma_bf16(acc[2*p  ], ahi, bh.x, bh.y);
                mma_bf16(acc[2*p+1], ahi, bh.z, bh.w);
                mma_bf16(acc[2*p  ], alo, bh.x, bh.y);
                mma_bf16(acc[2*p+1], alo, bh.z, bh.w);
                mma_bf16(acc[2*p  ], ahi, bl.x, bl.y);
                mma_bf16(acc[2*p+1], ahi, bl.z, bl.w);
            }
        }
    }
    __syncthreads();   // all warps done reading smem before epilogue overwrites
}

// ---------------- main kernel ----------------
__global__ void __launch_bounds__(THREADS, 3)
cin_mma_kernel(const float* __restrict__ x,
               const float* __restrict__ b0, const float* __restrict__ b1,
               const float* __restrict__ b2, const float* __restrict__ wl,
               float* __restrict__ out)
{
    extern __shared__ uint8_t smraw[];
    float* Xs = (float*)(smraw + SM_XS);
    float* Ps = (float*)(smraw + SM_PS);
    uint8_t* wb0 = smraw + SM_W0;
    uint8_t* wb1 = smraw + SM_W1;
    const uint32_t wb0u = smem_u32(wb0);
    const uint32_t wb1u = smem_u32(wb1);

    const int tid   = threadIdx.x;
    const int warp  = tid >> 5;
    const int lane  = tid & 31;
    const int q     = lane & 3;         // o-pair / k-pair selector
    const int rr    = lane >> 2;        // row-in-fragment
    const int warpT = warp & 3;         // t-group == local batch (16 rows)
    const int warpO = warp >> 2;        // o-group: 0 -> o 0..63, 1 -> o 64..127
    const int tl    = warpT * 16 + rr;  // rows tl, tl+8
    const int bbase = blockIdx.x * NB;

    // X tile: Xs[m][t], t = 16*local_batch + d   (40*64 elems)
    #pragma unroll 1
    for (int i = tid; i < 40 * 64; i += THREADS) {
        int m = i >> 6, t = i & 63;
        Xs[m * LDP + t] = __ldg(x + (size_t)(bbase + (t >> 4)) * 640 + m * 16 + (t & 15));
    }

    float pA = 0.0f;   // direct partial for batch warpT

    // ================= Layer 0: K=1600, P = X =================
    {
        float acc[8][4];
        run_layer<8, 8192, CHB0>(CH0, g_wpre + OFF0, Xs, Xs, wb0, wb1, wb0u, wb1u,
                                 warpO * 4096, acc, tid, lane, q, tl);
        #pragma unroll
        for (int nt = 0; nt < 8; ++nt) {
            int o = warpO * 64 + nt * 8 + q * 2;
            float bv0 = __ldg(b0 + o), bv1 = __ldg(b0 + o + 1);
            float v0 = fmaxf(acc[nt][0] + bv0, 0.0f);
            float v1 = fmaxf(acc[nt][1] + bv1, 0.0f);
            float v2 = fmaxf(acc[nt][2] + bv0, 0.0f);
            float v3 = fmaxf(acc[nt][3] + bv1, 0.0f);
            if (warpO == 0) {
                Ps[o * LDP + tl]           = v0;
                Ps[(o + 1) * LDP + tl]     = v1;
                Ps[o * LDP + tl + 8]       = v2;
                Ps[(o + 1) * LDP + tl + 8] = v3;
            } else {
                float w0v = __ldg(wl + o - 64), w1v = __ldg(wl + o - 63);
                pA += w0v * (v0 + v2) + w1v * (v1 + v3);
            }
        }
    }
    // ================= Layer 1: K=2560, P = Ps =================
    {
        float acc[8][4];
        run_layer<8, 8192, CHB1>(CH1, g_wpre + OFF1, Ps, Xs, wb0, wb1, wb0u, wb1u,
                                 warpO * 4096, acc, tid, lane, q, tl);
        #pragma unroll
        for (int nt = 0; nt < 8; ++nt) {
            int o = warpO * 64 + nt * 8 + q * 2;
            float bv0 = __ldg(b1 + o), bv1 = __ldg(b1 + o + 1);
            float v0 = fmaxf(acc[nt][0] + bv0, 0.0f);
            float v1 = fmaxf(acc[nt][1] + bv1, 0.0f);
            float v2 = fmaxf(acc[nt][2] + bv0, 0.0f);
            float v3 = fmaxf(acc[nt][3] + bv1, 0.0f);
            if (warpO == 0) {
                Ps[o * LDP + tl]           = v0;
                Ps[(o + 1) * LDP + tl]     = v1;
                Ps[o * LDP + tl + 8]       = v2;
                Ps[(o + 1) * LDP + tl + 8] = v3;
            } else {
                float w0v = __ldg(wl + o), w1v = __ldg(wl + o + 1);  // 64+(o-64)
                pA += w0v * (v0 + v2) + w1v * (v1 + v3);
            }
        }
    }
    // ========= Layer 2: K=2560, direct half only (o-split across warpO) =========
    {
        float acc[4][4];
        run_layer<4, 4096, CHB2>(CH2, g_wpre + OFF2, Ps, Xs, wb0, wb1, wb0u, wb1u,
                                 warpO * 2048, acc, tid, lane, q, tl);
        #pragma unroll
        for (int nt = 0; nt < 4; ++nt) {
            int oc = warpO * 32 + nt * 8 + q * 2;    // channel-in-half 0..63
            float bv0 = __ldg(b2 + 64 + oc), bv1 = __ldg(b2 + 65 + oc);
            float w0v = __ldg(wl + 128 + oc), w1v = __ldg(wl + 129 + oc);
            float v0 = fmaxf(acc[nt][0] + bv0, 0.0f);
            float v1 = fmaxf(acc[nt][1] + bv1, 0.0f);
            float v2 = fmaxf(acc[nt][2] + bv0, 0.0f);
            float v3 = fmaxf(acc[nt][3] + bv1, 0.0f);
            pA += w0v * (v0 + v2) + w1v * (v1 + v3);
        }
    }

    // ---- reduce to per-batch outputs (W buffers dead after final barrier) ----
    float* accS = (float*)(smraw + SM_W0);
    if (tid < NB) accS[tid] = 0.0f;
    __syncthreads();
    #pragma unroll
    for (int off = 16; off >= 1; off >>= 1)
        pA += __shfl_xor_sync(0xffffffffu, pA, off);
    if (lane == 0) atomicAdd(&accS[warpT], pA);
    __syncthreads();
    if (tid < NB) out[bbase + tid] = accS[tid];
}

extern "C" void kernel_launch(void* const* d_in, const int* in_sizes, int n_in,
                              void* d_out, int out_size)
{
    const float* x  = (const float*)d_in[0];
    const float* w0 = (const float*)d_in[1];
    const float* b0 = (const float*)d_in[2];
    const float* w1 = (const float*)d_in[3];
    const float* b1 = (const float*)d_in[4];
    const float* w2 = (const float*)d_in[5];
    const float* b2 = (const float*)d_in[6];
    const float* wl = (const float*)d_in[7];
    float* out = (float*)d_out;

    int prepN = WORDS0 + WORDS1 + WORDS2;
    prep_kernel<<<(prepN + 255) / 256, 256>>>(w0, w1, w2);

    cudaFuncSetAttribute(cin_mma_kernel,
                         cudaFuncAttributeMaxDynamicSharedMemorySize, SMEM_BYTES);
    cin_mma_kernel<<<2048 / NB, THREADS, SMEM_BYTES>>>(x, b0, b1, b2, wl, out);
}

// round 13
// speedup vs baseline: 1.4079x; 1.4079x over previous
#include <cuda_runtime.h>
#include <cuda_bf16.h>
#include <cstdint>

#define THREADS 256
#define NB 8                          // batches per CTA
#define LDP 136                       // padded smem row stride (floats)

// ---------------- smem byte layout ----------------
#define SM_XS 0                              // X : 40 x 136 f32 = 21760
#define SM_PS (40*LDP*4)                     // P : 64 x 136 f32 = 34816
#define SM_W0 (SM_PS + 64*LDP*4)             // W chunk32 buf0 (16KB)
#define SM_W1 (SM_W0 + 16384)                // W chunk32 buf1 (16KB)
#define SM_LUT (SM_W1 + 16384)               // layer-0 fold LUT: 832 u32
#define SMEM_BYTES (SM_LUT + 832*4)          // 92,672 bytes -> 2 CTAs/SM

// ---------------- prepped-W global scratch ----------------
// K=32 chunks. Per chunk: [s2=0|1 k16-step] x [tile-pairs] x [hi|lo] blocks.
// Block = 32 lanes x 16B: per lane {tile2p.b0, tile2p.b1, tile2p+1.b0, tile2p+1.b1}
#define NT0 16
#define NT1 16
#define NT2 8
#define CH0 26               // layer 0 FOLDED: K=820 -> 832 = 26 chunks
#define CH1 80
#define CH2 80
#define CHB0 (NT0*1024)      // 16384 B per chunk32
#define CHB1 (NT1*1024)      // 16384 B
#define CHB2 (NT2*1024)      // 8192 B
#define OFF0 0u
#define OFF1 (CH0*CHB0)                  // 425984
#define OFF2 (OFF1 + CH1*CHB1)           // 1736704
#define WPRE_BYTES (OFF2 + CH2*CHB2)     // 2392064

__device__ __align__(16) uint8_t g_wpre[WPRE_BYTES];
__device__ uint32_t g_lut0[832];             // packed (i<<8)|j per folded k

// ---------------- helpers ----------------
__device__ __forceinline__ uint32_t packb(float lo, float hi) {
    uint32_t r;
    asm("cvt.rn.bf16x2.f32 %0, %1, %2;" : "=r"(r) : "f"(hi), "f"(lo));
    return r;
}
__device__ __forceinline__ uint32_t prmt_hi(float a, float b) {
    uint32_t r;
    asm("prmt.b32 %0, %1, %2, 0x7632;"
        : "=r"(r) : "r"(__float_as_uint(a)), "r"(__float_as_uint(b)));
    return r;
}
__device__ __forceinline__ float trunc_hi(float v) {
    return __uint_as_float(__float_as_uint(v) & 0xFFFF0000u);
}
__device__ __forceinline__ void mma_bf16(float* c, const uint32_t* a,
                                         uint32_t b0, uint32_t b1) {
    asm volatile(
        "mma.sync.aligned.m16n8k16.row.col.f32.bf16.bf16.f32 "
        "{%0,%1,%2,%3}, {%4,%5,%6,%7}, {%8,%9}, {%0,%1,%2,%3};"
        : "+f"(c[0]), "+f"(c[1]), "+f"(c[2]), "+f"(c[3])
        : "r"(a[0]), "r"(a[1]), "r"(a[2]), "r"(a[3]), "r"(b0), "r"(b1));
}
__device__ __forceinline__ uint32_t smem_u32(const void* p) {
    uint32_t a;
    asm("{ .reg .u64 t; cvta.to.shared.u64 t, %1; cvt.u32.u64 %0, t; }" : "=r"(a) : "l"(p));
    return a;
}
__device__ __forceinline__ void cp_async16(uint32_t dst, const void* src) {
    asm volatile("cp.async.cg.shared.global [%0], [%1], 16;" :: "r"(dst), "l"(src));
}
#define CP_COMMIT() asm volatile("cp.async.commit_group;" ::: "memory")
#define CP_WAIT0()  asm volatile("cp.async.wait_group 0;" ::: "memory")

// folded-k -> (i,j), i<=j, row i holds (40-i) entries
__device__ __forceinline__ void fold_ij(int k, int& i, int& j) {
    i = 0; int rem = k;
    while (rem >= 40 - i) { rem -= (40 - i); ++i; }
    j = i + rem;
}
__device__ __forceinline__ float foldedW0(const float* __restrict__ w0, int o, int k) {
    if (k >= 820) return 0.0f;
    int i, j; fold_ij(k, i, j);
    float v = __ldg(w0 + (size_t)o * 1600 + i * 40 + j);
    if (i != j) v += __ldg(w0 + (size_t)o * 1600 + j * 40 + i);
    return v;
}

// ---------------- prep: fold L0 + truncation-split all W into paired blocks ----------------
#define WORDS0 (CH0*NT0*256)   // 106496
#define WORDS1 (CH1*NT1*256)   // 327680
#define WORDS2 (CH2*NT2*256)   // 163840
#define PREP_TOTAL (WORDS0 + WORDS1 + WORDS2 + 832)

__global__ void prep_kernel(const float* __restrict__ w0,
                            const float* __restrict__ w1,
                            const float* __restrict__ w2)
{
    int idx = blockIdx.x * blockDim.x + threadIdx.x;
    if (idx >= PREP_TOTAL) return;
    if (idx >= WORDS0 + WORDS1 + WORDS2) {          // LUT fill
        int k = idx - (WORDS0 + WORDS1 + WORDS2);
        uint32_t v = 0;
        if (k < 820) { int i, j; fold_ij(k, i, j); v = ((uint32_t)i << 8) | (uint32_t)j; }
        g_lut0[k] = v;
        return;
    }
    int lay, NT, li; uint32_t off, chb;
    const float* src = nullptr; int ld = 0, rowBase = 0;
    if (idx < WORDS0)                  { lay=0; NT=NT0; off=OFF0; chb=CHB0; li=idx; }
    else if (idx < WORDS0+WORDS1)      { lay=1; src=w1; NT=NT1; ld=2560; rowBase=0;  off=OFF1; chb=CHB1; li=idx-WORDS0; }
    else                               { lay=2; src=w2; NT=NT2; ld=2560; rowBase=64; off=OFF2; chb=CHB2; li=idx-WORDS0-WORDS1; }

    int perChunk = NT * 256;                  // b32 words per chunk32
    int c    = li / perChunk;
    int r    = li - c * perChunk;
    int half = NT * 128;                      // words per k16-step
    int s2   = r / half;
    int r2   = r - s2 * half;
    int pair = r2 >> 8;
    int r3   = r2 & 255;
    int sel  = r3 >> 7;                       // 0=hi, 1=lo
    int r4   = r3 & 127;
    int lane = r4 >> 2;
    int w4   = r4 & 3;                        // word within 16B
    int tile = pair * 2 + (w4 >> 1);
    int wsel = w4 & 1;                        // b0 (k+0..1) or b1 (k+8..9)

    int o = tile * 8 + (lane >> 2);
    int k = c * 32 + s2 * 16 + (lane & 3) * 2 + wsel * 8;
    float a, b;
    if (lay == 0) {
        a = foldedW0(w0, o, k);
        b = foldedW0(w0, o, k + 1);
    } else {
        a = __ldg(src + (size_t)(rowBase + o) * ld + k);
        b = __ldg(src + (size_t)(rowBase + o) * ld + k + 1);
    }
    uint32_t w;
    if (sel) w = packb(a - trunc_hi(a), b - trunc_hi(b));   // lo part
    else     w = prmt_hi(a, b);                              // hi part (exact)

    *(uint32_t*)(g_wpre + off + (size_t)c * chb
                 + s2 * (uint32_t)(NT / 2) * 1024 + pair * 1024 + sel * 512
                 + lane * 16 + w4 * 4) = w;
}

// ---------------- A-fragment builders (rows tl, tl+8) ----------------
__device__ __forceinline__ void packA(const float* zl, const float* zh,
                                      uint32_t* ahi, uint32_t* alo)
{
    ahi[0] = prmt_hi(zl[0], zl[1]);
    ahi[1] = prmt_hi(zh[0], zh[1]);
    ahi[2] = prmt_hi(zl[2], zl[3]);
    ahi[3] = prmt_hi(zh[2], zh[3]);
    alo[0] = packb(zl[0] - trunc_hi(zl[0]), zl[1] - trunc_hi(zl[1]));
    alo[1] = packb(zh[0] - trunc_hi(zh[0]), zh[1] - trunc_hi(zh[1]));
    alo[2] = packb(zl[2] - trunc_hi(zl[2]), zl[3] - trunc_hi(zl[3]));
    alo[3] = packb(zh[2] - trunc_hi(zh[2]), zh[3] - trunc_hi(zh[3]));
}

__device__ __forceinline__ void build_A(
    int step, const float* __restrict__ Pp, const float* __restrict__ Xs,
    int q, int tl, uint32_t* ahi, uint32_t* alo)
{
    const int k0 = step * 16 + q * 2;
    float zl[4], zh[4];
    #pragma unroll
    for (int e = 0; e < 4; ++e) {
        int k = k0 + (e & 1) + (e >> 1) * 8;   // {k0, k0+1, k0+8, k0+9}
        int h = k / 40;
        int m = k - h * 40;
        zl[e] = Pp[h * LDP + tl]     * Xs[m * LDP + tl];
        zh[e] = Pp[h * LDP + tl + 8] * Xs[m * LDP + tl + 8];
    }
    packA(zl, zh, ahi, alo);
}

// layer-0 folded: Z[k] = X[i]*X[j] via LUT
__device__ __forceinline__ void build_A0(
    int step, const float* __restrict__ Xs, const uint32_t* __restrict__ lutS,
    int q, int tl, uint32_t* ahi, uint32_t* alo)
{
    const int k0 = step * 16 + q * 2;
    float zl[4], zh[4];
    #pragma unroll
    for (int e = 0; e < 4; ++e) {
        int k = k0 + (e & 1) + (e >> 1) * 8;
        uint32_t ij = lutS[k];
        int i = (int)(ij >> 8), j = (int)(ij & 255u);
        zl[e] = Xs[i * LDP + tl]     * Xs[j * LDP + tl];
        zh[e] = Xs[i * LDP + tl + 8] * Xs[j * LDP + tl + 8];
    }
    packA(zl, zh, ahi, alo);
}

// ---------------- one CIN layer: warp = 16t x full-o, K32-streamed ----------------
template<int NTW, int STEPB, int CHB, bool L0>
__device__ __forceinline__ void run_layer(
    int nch, const uint8_t* __restrict__ wpre,
    const float* __restrict__ Pp, const float* __restrict__ Xs,
    const uint32_t* __restrict__ lutS,
    const uint8_t* __restrict__ wb0, const uint8_t* __restrict__ wb1,
    uint32_t wb0u, uint32_t wb1u,
    float (&acc)[NTW][4], int tid, int lane, int q, int tl)
{
    constexpr int NP  = NTW / 2;              // pairs per k16-step
    constexpr int CPT = CHB / 16 / THREADS;   // cp.async16 per thread

    #pragma unroll
    for (int nt = 0; nt < NTW; ++nt)
        #pragma unroll
        for (int j = 0; j < 4; ++j) acc[nt][j] = 0.0f;

    __syncthreads();   // previous layer's buffer reads / P writes / LUT copy complete

    #pragma unroll
    for (int i = 0; i < CPT; ++i) {
        int e = tid + i * THREADS;
        cp_async16(wb0u + e * 16, wpre + e * 16);
    }
    CP_COMMIT();

    #pragma unroll 1
    for (int c = 0; c < nch; ++c) {
        CP_WAIT0();
        __syncthreads();                      // chunk c visible; prev buffer reads done
        if (c + 1 < nch) {
            const uint8_t* src = wpre + (size_t)(c + 1) * CHB;
            uint32_t dst = ((c + 1) & 1) ? wb1u : wb0u;
            #pragma unroll
            for (int i = 0; i < CPT; ++i) {
                int e = tid + i * THREADS;
                cp_async16(dst + e * 16, src + e * 16);
            }
        }
        CP_COMMIT();                          // overlaps with compute below
        const uint8_t* __restrict__ wb = (c & 1) ? wb1 : wb0;

        #pragma unroll
        for (int s2 = 0; s2 < 2; ++s2) {
            uint32_t ahi[4], alo[4];
            if (L0) build_A0(c * 2 + s2, Xs, lutS, q, tl, ahi, alo);
            else    build_A (c * 2 + s2, Pp, Xs,   q, tl, ahi, alo);

            const uint8_t* __restrict__ wbs = wb + s2 * STEPB;

            #pragma unroll
            for (int p = 0; p < NP; ++p) {
                const uint4 bh = *(const uint4*)(wbs + p * 1024 + lane * 16);
                const uint4 bl = *(const uint4*)(wbs + p * 1024 + 512 + lane * 16);
                // per-acc order: hi*bh, lo*bh, hi*bl
                mma_bf16(acc[2*p  ], ahi, bh.x, bh.y);
                mma_bf16(acc[2*p+1], ahi, bh.z, bh.w);
                mma_bf16(acc[2*p  ], alo, bh.x, bh.y);
                mma_bf16(acc[2*p+1], alo, bh.z, bh.w);
                mma_bf16(acc[2*p  ], ahi, bl.x, bl.y);
                mma_bf16(acc[2*p+1], ahi, bl.z, bl.w);
            }
        }
    }
    __syncthreads();   // all warps done reading smem before epilogue overwrites
}

// ---------------- main kernel ----------------
__global__ void __launch_bounds__(THREADS, 2)
cin_mma_kernel(const float* __restrict__ x,
               const float* __restrict__ b0, const float* __restrict__ b1,
               const float* __restrict__ b2, const float* __restrict__ wl,
               float* __restrict__ out)
{
    extern __shared__ uint8_t smraw[];
    float* Xs = (float*)(smraw + SM_XS);
    float* Ps = (float*)(smraw + SM_PS);
    uint8_t* wb0 = smraw + SM_W0;
    uint8_t* wb1 = smraw + SM_W1;
    uint32_t* lutS = (uint32_t*)(smraw + SM_LUT);
    const uint32_t wb0u = smem_u32(wb0);
    const uint32_t wb1u = smem_u32(wb1);

    const int tid  = threadIdx.x;
    const int warp = tid >> 5;        // warp == local batch (0..7)
    const int lane = tid & 31;
    const int q    = lane & 3;        // o-pair / k-pair selector
    const int rr   = lane >> 2;       // row-in-fragment
    const int tl   = warp * 16 + rr;  // rows tl, tl+8
    const int bbase = blockIdx.x * NB;

    // X tile: Xs[m][t], t = 16*local_batch + d   (40*128 elems)
    #pragma unroll 1
    for (int i = tid; i < 40 * 128; i += THREADS) {
        int m = i >> 7, t = i & 127;
        Xs[m * LDP + t] = __ldg(x + (size_t)(bbase + (t >> 4)) * 640 + m * 16 + (t & 15));
    }
    // LUT copy (ordered by run_layer's leading barrier)
    #pragma unroll 1
    for (int i = tid; i < 832; i += THREADS) lutS[i] = g_lut0[i];

    float pl = 0.0f, ph = 0.0f;       // direct partials for rows tl, tl+8

    // ========== Layer 0: folded K=832, Z = X.X (symmetric) ==========
    {
        float acc[16][4];
        run_layer<16, 8192, CHB0, true>(CH0, g_wpre + OFF0, Xs, Xs, lutS,
                                        wb0, wb1, wb0u, wb1u, acc, tid, lane, q, tl);
        #pragma unroll
        for (int nt = 0; nt < 16; ++nt) {
            int o = nt * 8 + q * 2;
            float bv0 = __ldg(b0 + o), bv1 = __ldg(b0 + o + 1);
            float v0 = fmaxf(acc[nt][0] + bv0, 0.0f);
            float v1 = fmaxf(acc[nt][1] + bv1, 0.0f);
            float v2 = fmaxf(acc[nt][2] + bv0, 0.0f);
            float v3 = fmaxf(acc[nt][3] + bv1, 0.0f);
            if (nt < 8) {
                Ps[o * LDP + tl]           = v0;
                Ps[(o + 1) * LDP + tl]     = v1;
                Ps[o * LDP + tl + 8]       = v2;
                Ps[(o + 1) * LDP + tl + 8] = v3;
            } else {
                float w0v = __ldg(wl + o - 64), w1v = __ldg(wl + o - 63);
                pl += w0v * v0 + w1v * v1;
                ph += w0v * v2 + w1v * v3;
            }
        }
    }
    // ================= Layer 1: K=2560, P = Ps =================
    {
        float acc[16][4];
        run_layer<16, 8192, CHB1, false>(CH1, g_wpre + OFF1, Ps, Xs, lutS,
                                         wb0, wb1, wb0u, wb1u, acc, tid, lane, q, tl);
        #pragma unroll
        for (int nt = 0; nt < 16; ++nt) {
            int o = nt * 8 + q * 2;
            float bv0 = __ldg(b1 + o), bv1 = __ldg(b1 + o + 1);
            float v0 = fmaxf(acc[nt][0] + bv0, 0.0f);
            float v1 = fmaxf(acc[nt][1] + bv1, 0.0f);
            float v2 = fmaxf(acc[nt][2] + bv0, 0.0f);
            float v3 = fmaxf(acc[nt][3] + bv1, 0.0f);
            if (nt < 8) {
                Ps[o * LDP + tl]           = v0;
                Ps[(o + 1) * LDP + tl]     = v1;
                Ps[o * LDP + tl + 8]       = v2;
                Ps[(o + 1) * LDP + tl + 8] = v3;
            } else {
                float w0v = __ldg(wl + o), w1v = __ldg(wl + o + 1);  // 64 + (o-64)
                pl += w0v * v0 + w1v * v1;
                ph += w0v * v2 + w1v * v3;
            }
        }
    }
    // ========= Layer 2: K=2560, direct half only (N=64) =========
    {
        float acc[8][4];
        run_layer<8, 4096, CHB2, false>(CH2, g_wpre + OFF2, Ps, Xs, lutS,
                                        wb0, wb1, wb0u, wb1u, acc, tid, lane, q, tl);
        #pragma unroll
        for (int nt = 0; nt < 8; ++nt) {
            int oc = nt * 8 + q * 2;                 // channel-in-half 0..63
            float bv0 = __ldg(b2 + 64 + oc), bv1 = __ldg(b2 + 65 + oc);
            float v0 = fmaxf(acc[nt][0] + bv0, 0.0f);
            float v1 = fmaxf(acc[nt][1] + bv1, 0.0f);
            float v2 = fmaxf(acc[nt][2] + bv0, 0.0f);
            float v3 = fmaxf(acc[nt][3] + bv1, 0.0f);
            float w0v = __ldg(wl + 128 + oc), w1v = __ldg(wl + 129 + oc);
            pl += w0v * v0 + w1v * v1;
            ph += w0v * v2 + w1v * v3;
        }
    }

    // ---- per-batch reduction: warp == batch, sum over its 16 t's ----
    float p = pl + ph;
    #pragma unroll
    for (int off = 16; off >= 1; off >>= 1)
        p += __shfl_xor_sync(0xffffffffu, p, off);
    if (lane == 0) out[bbase + warp] = p;
}

extern "C" void kernel_launch(void* const* d_in, const int* in_sizes, int n_in,
                              void* d_out, int out_size)
{
    const float* x  = (const float*)d_in[0];
    const float* w0 = (const float*)d_in[1];
    const float* b0 = (const float*)d_in[2];
    const float* w1 = (const float*)d_in[3];
    const float* b1 = (const float*)d_in[4];
    const float* w2 = (const float*)d_in[5];
    const float* b2 = (const float*)d_in[6];
    const float* wl = (const float*)d_in[7];
    float* out = (float*)d_out;

    prep_kernel<<<(PREP_TOTAL + 255) / 256, 256>>>(w0, w1, w2);

    cudaFuncSetAttribute(cin_mma_kernel,
                         cudaFuncAttributeMaxDynamicSharedMemorySize, SMEM_BYTES);
    cin_mma_kernel<<<2048 / NB, THREADS, SMEM_BYTES>>>(x, b0, b1, b2, wl, out);
}

// round 14
// speedup vs baseline: 1.8308x; 1.3004x over previous
#include <cuda_runtime.h>
#include <cuda_fp16.h>
#include <cstdint>

#define THREADS 256
#define NB 8                          // batches per CTA
#define LDP 136                       // padded smem row stride (floats)

// ---------------- smem byte layout ----------------
#define SM_XS 0                              // X : 40 x 136 f32 = 21760
#define SM_PS (40*LDP*4)                     // P : 64 x 136 f32 = 34816
#define SM_W0 (SM_PS + 64*LDP*4)             // W chunk32 buf0 (8KB, fp16 single)
#define SM_W1 (SM_W0 + 8192)                 // W chunk32 buf1 (8KB)
#define SM_LUT (SM_W1 + 8192)                // layer-0 fold LUT: 832 u32
#define SMEM_BYTES (SM_LUT + 832*4)          // 76,288 bytes -> 2 CTAs/SM

// ---------------- prepped-W global scratch (fp16, single precision level) ----------------
// K=32 chunks. Per chunk: [s2=0|1 k16-step] x [tile-pairs] blocks.
// Block = 32 lanes x 16B: per lane {tile2p.b0, tile2p.b1, tile2p+1.b0, tile2p+1.b1}
#define NT0 16
#define NT1 16
#define NT2 8
#define CH0 26               // layer 0 FOLDED: K=820 -> 832 = 26 chunks
#define CH1 80
#define CH2 80
#define CHB0 (NT0*512)       // 8192 B per chunk32
#define CHB1 (NT1*512)       // 8192 B
#define CHB2 (NT2*512)       // 4096 B
#define OFF0 0u
#define OFF1 (CH0*CHB0)                  // 212992
#define OFF2 (OFF1 + CH1*CHB1)           // 868352
#define WPRE_BYTES (OFF2 + CH2*CHB2)     // 1195712

__device__ __align__(16) uint8_t g_wpre[WPRE_BYTES];
__device__ uint32_t g_lut0[832];             // packed (i<<8)|j per folded k

// ---------------- helpers ----------------
// pack two floats to fp16x2 (round-nearest); first arg -> low half (element k)
__device__ __forceinline__ uint32_t packh(float lo, float hi) {
    __half2 h = __floats2half2_rn(lo, hi);
    return *(uint32_t*)&h;
}
// keep top 10 mantissa bits -> exactly fp16-representable (truncation split)
__device__ __forceinline__ float trunc_h10(float v) {
    return __uint_as_float(__float_as_uint(v) & 0xFFFFE000u);
}
__device__ __forceinline__ void mma_f16(float* c, const uint32_t* a,
                                        uint32_t b0, uint32_t b1) {
    asm volatile(
        "mma.sync.aligned.m16n8k16.row.col.f32.f16.f16.f32 "
        "{%0,%1,%2,%3}, {%4,%5,%6,%7}, {%8,%9}, {%0,%1,%2,%3};"
        : "+f"(c[0]), "+f"(c[1]), "+f"(c[2]), "+f"(c[3])
        : "r"(a[0]), "r"(a[1]), "r"(a[2]), "r"(a[3]), "r"(b0), "r"(b1));
}
__device__ __forceinline__ uint32_t smem_u32(const void* p) {
    uint32_t a;
    asm("{ .reg .u64 t; cvta.to.shared.u64 t, %1; cvt.u32.u64 %0, t; }" : "=r"(a) : "l"(p));
    return a;
}
__device__ __forceinline__ void cp_async16(uint32_t dst, const void* src) {
    asm volatile("cp.async.cg.shared.global [%0], [%1], 16;" :: "r"(dst), "l"(src));
}
#define CP_COMMIT() asm volatile("cp.async.commit_group;" ::: "memory")
#define CP_WAIT0()  asm volatile("cp.async.wait_group 0;" ::: "memory")

// folded-k -> (i,j), i<=j, row i holds (40-i) entries
__device__ __forceinline__ void fold_ij(int k, int& i, int& j) {
    i = 0; int rem = k;
    while (rem >= 40 - i) { rem -= (40 - i); ++i; }
    j = i + rem;
}
__device__ __forceinline__ float foldedW0(const float* __restrict__ w0, int o, int k) {
    if (k >= 820) return 0.0f;
    int i, j; fold_ij(k, i, j);
    float v = __ldg(w0 + (size_t)o * 1600 + i * 40 + j);
    if (i != j) v += __ldg(w0 + (size_t)o * 1600 + j * 40 + i);
    return v;
}

// ---------------- prep: fold L0 + fp16-round all W into paired blocks ----------------
#define WORDS0 (CH0*NT0*128)   // 53248
#define WORDS1 (CH1*NT1*128)   // 163840
#define WORDS2 (CH2*NT2*128)   // 81920
#define PREP_TOTAL (WORDS0 + WORDS1 + WORDS2 + 832)

__global__ void prep_kernel(const float* __restrict__ w0,
                            const float* __restrict__ w1,
                            const float* __restrict__ w2)
{
    int idx = blockIdx.x * blockDim.x + threadIdx.x;
    if (idx >= PREP_TOTAL) return;
    if (idx >= WORDS0 + WORDS1 + WORDS2) {          // LUT fill
        int k = idx - (WORDS0 + WORDS1 + WORDS2);
        uint32_t v = 0;
        if (k < 820) { int i, j; fold_ij(k, i, j); v = ((uint32_t)i << 8) | (uint32_t)j; }
        g_lut0[k] = v;
        return;
    }
    int lay, NT, li; uint32_t off, chb;
    const float* src = nullptr; int ld = 0, rowBase = 0;
    if (idx < WORDS0)                  { lay=0; NT=NT0; off=OFF0; chb=CHB0; li=idx; }
    else if (idx < WORDS0+WORDS1)      { lay=1; src=w1; NT=NT1; ld=2560; rowBase=0;  off=OFF1; chb=CHB1; li=idx-WORDS0; }
    else                               { lay=2; src=w2; NT=NT2; ld=2560; rowBase=64; off=OFF2; chb=CHB2; li=idx-WORDS0-WORDS1; }

    int perChunk = NT * 128;                  // b32 words per chunk32
    int c    = li / perChunk;
    int r    = li - c * perChunk;
    int half = NT * 64;                       // words per k16-step
    int s2   = r / half;
    int r2   = r - s2 * half;
    int pair = r2 >> 7;                       // 128 words per pair block
    int r3   = r2 & 127;
    int lane = r3 >> 2;
    int w4   = r3 & 3;                        // word within 16B
    int tile = pair * 2 + (w4 >> 1);
    int wsel = w4 & 1;                        // b0 (k+0..1) or b1 (k+8..9)

    int o = tile * 8 + (lane >> 2);
    int k = c * 32 + s2 * 16 + (lane & 3) * 2 + wsel * 8;
    float a, b;
    if (lay == 0) {
        a = foldedW0(w0, o, k);
        b = foldedW0(w0, o, k + 1);
    } else {
        a = __ldg(src + (size_t)(rowBase + o) * ld + k);
        b = __ldg(src + (size_t)(rowBase + o) * ld + k + 1);
    }
    uint32_t w = packh(a, b);                 // fp16 round-nearest, low half = k

    *(uint32_t*)(g_wpre + off + (size_t)c * chb
                 + s2 * (uint32_t)(NT / 2) * 512 + pair * 512
                 + lane * 16 + w4 * 4) = w;
}

// ---------------- A-fragment builders (rows tl, tl+8) ----------------
__device__ __forceinline__ void packA(const float* zl, const float* zh,
                                      uint32_t* ahi, uint32_t* alo)
{
    float hl0 = trunc_h10(zl[0]), hl1 = trunc_h10(zl[1]);
    float hl2 = trunc_h10(zl[2]), hl3 = trunc_h10(zl[3]);
    float hh0 = trunc_h10(zh[0]), hh1 = trunc_h10(zh[1]);
    float hh2 = trunc_h10(zh[2]), hh3 = trunc_h10(zh[3]);
    ahi[0] = packh(hl0, hl1);                 // exact (10-bit mantissa)
    ahi[1] = packh(hh0, hh1);
    ahi[2] = packh(hl2, hl3);
    ahi[3] = packh(hh2, hh3);
    alo[0] = packh(zl[0] - hl0, zl[1] - hl1); // residual, fp16-rounded
    alo[1] = packh(zh[0] - hh0, zh[1] - hh1);
    alo[2] = packh(zl[2] - hl2, zl[3] - hl3);
    alo[3] = packh(zh[2] - hh2, zh[3] - hh3);
}

__device__ __forceinline__ void build_A(
    int step, const float* __restrict__ Pp, const float* __restrict__ Xs,
    int q, int tl, uint32_t* ahi, uint32_t* alo)
{
    const int k0 = step * 16 + q * 2;
    float zl[4], zh[4];
    #pragma unroll
    for (int e = 0; e < 4; ++e) {
        int k = k0 + (e & 1) + (e >> 1) * 8;   // {k0, k0+1, k0+8, k0+9}
        int h = k / 40;
        int m = k - h * 40;
        zl[e] = Pp[h * LDP + tl]     * Xs[m * LDP + tl];
        zh[e] = Pp[h * LDP + tl + 8] * Xs[m * LDP + tl + 8];
    }
    packA(zl, zh, ahi, alo);
}

// layer-0 folded: Z[k] = X[i]*X[j] via LUT
__device__ __forceinline__ void build_A0(
    int step, const float* __restrict__ Xs, const uint32_t* __restrict__ lutS,
    int q, int tl, uint32_t* ahi, uint32_t* alo)
{
    const int k0 = step * 16 + q * 2;
    float zl[4], zh[4];
    #pragma unroll
    for (int e = 0; e < 4; ++e) {
        int k = k0 + (e & 1) + (e >> 1) * 8;
        uint32_t ij = lutS[k];
        int i = (int)(ij >> 8), j = (int)(ij & 255u);
        zl[e] = Xs[i * LDP + tl]     * Xs[j * LDP + tl];
        zh[e] = Xs[i * LDP + tl + 8] * Xs[j * LDP + tl + 8];
    }
    packA(zl, zh, ahi, alo);
}

// ---------------- one CIN layer: warp = 16t x full-o, K32-streamed, 2 MMAs/tile ----------------
template<int NTW, int STEPB, int CHB, bool L0>
__device__ __forceinline__ void run_layer(
    int nch, const uint8_t* __restrict__ wpre,
    const float* __restrict__ Pp, const float* __restrict__ Xs,
    const uint32_t* __restrict__ lutS,
    const uint8_t* __restrict__ wb0, const uint8_t* __restrict__ wb1,
    uint32_t wb0u, uint32_t wb1u,
    float (&acc)[NTW][4], int tid, int lane, int q, int tl)
{
    constexpr int NP  = NTW / 2;              // pairs per k16-step
    constexpr int CPT = CHB / 16 / THREADS;   // cp.async16 per thread (2 or 1)

    #pragma unroll
    for (int nt = 0; nt < NTW; ++nt)
        #pragma unroll
        for (int j = 0; j < 4; ++j) acc[nt][j] = 0.0f;

    __syncthreads();   // previous layer's buffer reads / P writes / LUT copy complete

    #pragma unroll
    for (int i = 0; i < CPT; ++i) {
        int e = tid + i * THREADS;
        cp_async16(wb0u + e * 16, wpre + e * 16);
    }
    CP_COMMIT();

    #pragma unroll 1
    for (int c = 0; c < nch; ++c) {
        CP_WAIT0();
        __syncthreads();                      // chunk c visible; prev buffer reads done
        if (c + 1 < nch) {
            const uint8_t* src = wpre + (size_t)(c + 1) * CHB;
            uint32_t dst = ((c + 1) & 1) ? wb1u : wb0u;
            #pragma unroll
            for (int i = 0; i < CPT; ++i) {
                int e = tid + i * THREADS;
                cp_async16(dst + e * 16, src + e * 16);
            }
        }
        CP_COMMIT();                          // overlaps with compute below
        const uint8_t* __restrict__ wb = (c & 1) ? wb1 : wb0;

        #pragma unroll
        for (int s2 = 0; s2 < 2; ++s2) {
            uint32_t ahi[4], alo[4];
            if (L0) build_A0(c * 2 + s2, Xs, lutS, q, tl, ahi, alo);
            else    build_A (c * 2 + s2, Pp, Xs,   q, tl, ahi, alo);

            const uint8_t* __restrict__ wbs = wb + s2 * STEPB;

            #pragma unroll
            for (int p = 0; p < NP; ++p) {
                const uint4 bh = *(const uint4*)(wbs + p * 512 + lane * 16);
                // per-acc order: hi*B then lo*B
                mma_f16(acc[2*p  ], ahi, bh.x, bh.y);
                mma_f16(acc[2*p+1], ahi, bh.z, bh.w);
                mma_f16(acc[2*p  ], alo, bh.x, bh.y);
                mma_f16(acc[2*p+1], alo, bh.z, bh.w);
            }
        }
    }
    __syncthreads();   // all warps done reading smem before epilogue overwrites
}

// ---------------- main kernel ----------------
__global__ void __launch_bounds__(THREADS, 2)
cin_mma_kernel(const float* __restrict__ x,
               const float* __restrict__ b0, const float* __restrict__ b1,
               const float* __restrict__ b2, const float* __restrict__ wl,
               float* __restrict__ out)
{
    extern __shared__ uint8_t smraw[];
    float* Xs = (float*)(smraw + SM_XS);
    float* Ps = (float*)(smraw + SM_PS);
    uint8_t* wb0 = smraw + SM_W0;
    uint8_t* wb1 = smraw + SM_W1;
    uint32_t* lutS = (uint32_t*)(smraw + SM_LUT);
    const uint32_t wb0u = smem_u32(wb0);
    const uint32_t wb1u = smem_u32(wb1);

    const int tid  = threadIdx.x;
    const int warp = tid >> 5;        // warp == local batch (0..7)
    const int lane = tid & 31;
    const int q    = lane & 3;        // o-pair / k-pair selector
    const int rr   = lane >> 2;       // row-in-fragment
    const int tl   = warp * 16 + rr;  // rows tl, tl+8
    const int bbase = blockIdx.x * NB;

    // X tile: Xs[m][t], t = 16*local_batch + d   (40*128 elems)
    #pragma unroll 1
    for (int i = tid; i < 40 * 128; i += THREADS) {
        int m = i >> 7, t = i & 127;
        Xs[m * LDP + t] = __ldg(x + (size_t)(bbase + (t >> 4)) * 640 + m * 16 + (t & 15));
    }
    // LUT copy (ordered by run_layer's leading barrier)
    #pragma unroll 1
    for (int i = tid; i < 832; i += THREADS) lutS[i] = g_lut0[i];

    float pl = 0.0f, ph = 0.0f;       // direct partials for rows tl, tl+8

    // ========== Layer 0: folded K=832, Z = X.X (symmetric) ==========
    {
        float acc[16][4];
        run_layer<16, 4096, CHB0, true>(CH0, g_wpre + OFF0, Xs, Xs, lutS,
                                        wb0, wb1, wb0u, wb1u, acc, tid, lane, q, tl);
        #pragma unroll
        for (int nt = 0; nt < 16; ++nt) {
            int o = nt * 8 + q * 2;
            float bv0 = __ldg(b0 + o), bv1 = __ldg(b0 + o + 1);
            float v0 = fmaxf(acc[nt][0] + bv0, 0.0f);
            float v1 = fmaxf(acc[nt][1] + bv1, 0.0f);
            float v2 = fmaxf(acc[nt][2] + bv0, 0.0f);
            float v3 = fmaxf(acc[nt][3] + bv1, 0.0f);
            if (nt < 8) {
                Ps[o * LDP + tl]           = v0;
                Ps[(o + 1) * LDP + tl]     = v1;
                Ps[o * LDP + tl + 8]       = v2;
                Ps[(o + 1) * LDP + tl + 8] = v3;
            } else {
                float w0v = __ldg(wl + o - 64), w1v = __ldg(wl + o - 63);
                pl += w0v * v0 + w1v * v1;
                ph += w0v * v2 + w1v * v3;
            }
        }
    }
    // ================= Layer 1: K=2560, P = Ps =================
    {
        float acc[16][4];
        run_layer<16, 4096, CHB1, false>(CH1, g_wpre + OFF1, Ps, Xs, lutS,
                                         wb0, wb1, wb0u, wb1u, acc, tid, lane, q, tl);
        #pragma unroll
        for (int nt = 0; nt < 16; ++nt) {
            int o = nt * 8 + q * 2;
            float bv0 = __ldg(b1 + o), bv1 = __ldg(b1 + o + 1);
            float v0 = fmaxf(acc[nt][0] + bv0, 0.0f);
            float v1 = fmaxf(acc[nt][1] + bv1, 0.0f);
            float v2 = fmaxf(acc[nt][2] + bv0, 0.0f);
            float v3 = fmaxf(acc[nt][3] + bv1, 0.0f);
            if (nt < 8) {
                Ps[o * LDP + tl]           = v0;
                Ps[(o + 1) * LDP + tl]     = v1;
                Ps[o * LDP + tl + 8]       = v2;
                Ps[(o + 1) * LDP + tl + 8] = v3;
            } else {
                float w0v = __ldg(wl + o), w1v = __ldg(wl + o + 1);  // 64 + (o-64)
                pl += w0v * v0 + w1v * v1;
                ph += w0v * v2 + w1v * v3;
            }
        }
    }
    // ========= Layer 2: K=2560, direct half only (N=64) =========
    {
        float acc[8][4];
        run_layer<8, 2048, CHB2, false>(CH2, g_wpre + OFF2, Ps, Xs, lutS,
                                        wb0, wb1, wb0u, wb1u, acc, tid, lane, q, tl);
        #pragma unroll
        for (int nt = 0; nt < 8; ++nt) {
            int oc = nt * 8 + q * 2;                 // channel-in-half 0..63
            float bv0 = __ldg(b2 + 64 + oc), bv1 = __ldg(b2 + 65 + oc);
            float v0 = fmaxf(acc[nt][0] + bv0, 0.0f);
            float v1 = fmaxf(acc[nt][1] + bv1, 0.0f);
            float v2 = fmaxf(acc[nt][2] + bv0, 0.0f);
            float v3 = fmaxf(acc[nt][3] + bv1, 0.0f);
            float w0v = __ldg(wl + 128 + oc), w1v = __ldg(wl + 129 + oc);
            pl += w0v * v0 + w1v * v1;
            ph += w0v * v2 + w1v * v3;
        }
    }

    // ---- per-batch reduction: warp == batch, sum over its 16 t's ----
    float p = pl + ph;
    #pragma unroll
    for (int off = 16; off >= 1; off >>= 1)
        p += __shfl_xor_sync(0xffffffffu, p, off);
    if (lane == 0) out[bbase + warp] = p;
}

extern "C" void kernel_launch(void* const* d_in, const int* in_sizes, int n_in,
                              void* d_out, int out_size)
{
    const float* x  = (const float*)d_in[0];
    const float* w0 = (const float*)d_in[1];
    const float* b0 = (const float*)d_in[2];
    const float* w1 = (const float*)d_in[3];
    const float* b1 = (const float*)d_in[4];
    const float* w2 = (const float*)d_in[5];
    const float* b2 = (const float*)d_in[6];
    const float* wl = (const float*)d_in[7];
    float* out = (float*)d_out;

    prep_kernel<<<(PREP_TOTAL + 255) / 256, 256>>>(w0, w1, w2);

    cudaFuncSetAttribute(cin_mma_kernel,
                         cudaFuncAttributeMaxDynamicSharedMemorySize, SMEM_BYTES);
    cin_mma_kernel<<<2048 / NB, THREADS, SMEM_BYTES>>>(x, b0, b1, b2, wl, out);
}

// round 15
// speedup vs baseline: 2.6431x; 1.4437x over previous
#include <cuda_runtime.h>
#include <cuda_fp16.h>
#include <cstdint>

#define THREADS 256
#define NB 8                          // batches per CTA
#define LDP 136                       // padded smem row stride (floats)

// ---------------- smem byte layout ----------------
#define SM_XS 0                              // X : 40 x 136 f32 = 21760
#define SM_PS (40*LDP*4)                     // P : 64 x 136 f32 = 34816
#define SM_W0 (SM_PS + 64*LDP*4)             // W chunk64 buf0 (16KB max)
#define SM_W1 (SM_W0 + 16384)                // W chunk64 buf1 (16KB max)
#define SM_LUT (SM_W1 + 16384)               // layer-0 fold LUT: 832 u32
#define SMEM_BYTES (SM_LUT + 832*4)          // 92,672 bytes -> 2 CTAs/SM

// ---------------- prepped-W global scratch (fp16 single) ----------------
// chunk32 units in memory. Per chunk32: [s2=0|1 k16-step] x [tile-pairs] blocks.
// Pair block = 32 lanes x 16B: {tile2p.b0, tile2p.b1, tile2p+1.b0, tile2p+1.b1}
#define NT0 16
#define NT1 16
#define NT2 8
#define CH0 26               // layer 0 FOLDED: K=820 -> 832 = 26 chunk32s
#define CH1 80
#define CH2 80
#define CHB0 (NT0*512)       // 8192 B per chunk32
#define CHB1 (NT1*512)       // 8192 B
#define CHB2 (NT2*512)       // 4096 B
#define OFF0 0u
#define OFF1 (CH0*CHB0)                  // 212992
#define OFF2 (OFF1 + CH1*CHB1)           // 868352
#define WPRE_BYTES (OFF2 + CH2*CHB2)     // 1195712

__device__ __align__(16) uint8_t g_wpre[WPRE_BYTES];
__device__ uint32_t g_lut0[832];             // packed (i<<8)|j per folded k

// ---------------- helpers ----------------
__device__ __forceinline__ uint32_t packh(float lo, float hi) {
    __half2 h = __floats2half2_rn(lo, hi);
    return *(uint32_t*)&h;
}
__device__ __forceinline__ void mma_f16(float* c, const uint32_t* a,
                                        uint32_t b0, uint32_t b1) {
    asm volatile(
        "mma.sync.aligned.m16n8k16.row.col.f32.f16.f16.f32 "
        "{%0,%1,%2,%3}, {%4,%5,%6,%7}, {%8,%9}, {%0,%1,%2,%3};"
        : "+f"(c[0]), "+f"(c[1]), "+f"(c[2]), "+f"(c[3])
        : "r"(a[0]), "r"(a[1]), "r"(a[2]), "r"(a[3]), "r"(b0), "r"(b1));
}
__device__ __forceinline__ uint32_t smem_u32(const void* p) {
    uint32_t a;
    asm("{ .reg .u64 t; cvta.to.shared.u64 t, %1; cvt.u32.u64 %0, t; }" : "=r"(a) : "l"(p));
    return a;
}
__device__ __forceinline__ void cp_async16(uint32_t dst, const void* src) {
    asm volatile("cp.async.cg.shared.global [%0], [%1], 16;" :: "r"(dst), "l"(src));
}
#define CP_COMMIT() asm volatile("cp.async.commit_group;" ::: "memory")
#define CP_WAIT0()  asm volatile("cp.async.wait_group 0;" ::: "memory")

// folded-k -> (i,j), i<=j, row i holds (40-i) entries
__device__ __forceinline__ void fold_ij(int k, int& i, int& j) {
    i = 0; int rem = k;
    while (rem >= 40 - i) { rem -= (40 - i); ++i; }
    j = i + rem;
}
__device__ __forceinline__ float foldedW0(const float* __restrict__ w0, int o, int k) {
    if (k >= 820) return 0.0f;
    int i, j; fold_ij(k, i, j);
    float v = __ldg(w0 + (size_t)o * 1600 + i * 40 + j);
    if (i != j) v += __ldg(w0 + (size_t)o * 1600 + j * 40 + i);
    return v;
}

// ---------------- prep: fold L0 + fp16-round all W into paired blocks ----------------
#define WORDS0 (CH0*NT0*128)   // 53248
#define WORDS1 (CH1*NT1*128)   // 163840
#define WORDS2 (CH2*NT2*128)   // 81920
#define PREP_TOTAL (WORDS0 + WORDS1 + WORDS2 + 832)

__global__ void prep_kernel(const float* __restrict__ w0,
                            const float* __restrict__ w1,
                            const float* __restrict__ w2)
{
    int idx = blockIdx.x * blockDim.x + threadIdx.x;
    if (idx >= PREP_TOTAL) return;
    if (idx >= WORDS0 + WORDS1 + WORDS2) {          // LUT fill
        int k = idx - (WORDS0 + WORDS1 + WORDS2);
        uint32_t v = 0;
        if (k < 820) { int i, j; fold_ij(k, i, j); v = ((uint32_t)i << 8) | (uint32_t)j; }
        g_lut0[k] = v;
        return;
    }
    int lay, NT, li; uint32_t off, chb;
    const float* src = nullptr; int ld = 0, rowBase = 0;
    if (idx < WORDS0)                  { lay=0; NT=NT0; off=OFF0; chb=CHB0; li=idx; }
    else if (idx < WORDS0+WORDS1)      { lay=1; src=w1; NT=NT1; ld=2560; rowBase=0;  off=OFF1; chb=CHB1; li=idx-WORDS0; }
    else                               { lay=2; src=w2; NT=NT2; ld=2560; rowBase=64; off=OFF2; chb=CHB2; li=idx-WORDS0-WORDS1; }

    int perChunk = NT * 128;                  // b32 words per chunk32
    int c    = li / perChunk;
    int r    = li - c * perChunk;
    int half = NT * 64;                       // words per k16-step
    int s2   = r / half;
    int r2   = r - s2 * half;
    int pair = r2 >> 7;                       // 128 words per pair block
    int r3   = r2 & 127;
    int lane = r3 >> 2;
    int w4   = r3 & 3;                        // word within 16B
    int tile = pair * 2 + (w4 >> 1);
    int wsel = w4 & 1;                        // b0 (k+0..1) or b1 (k+8..9)

    int o = tile * 8 + (lane >> 2);
    int k = c * 32 + s2 * 16 + (lane & 3) * 2 + wsel * 8;
    float a, b;
    if (lay == 0) {
        a = foldedW0(w0, o, k);
        b = foldedW0(w0, o, k + 1);
    } else {
        a = __ldg(src + (size_t)(rowBase + o) * ld + k);
        b = __ldg(src + (size_t)(rowBase + o) * ld + k + 1);
    }
    uint32_t w = packh(a, b);                 // fp16 round-nearest, low half = k

    *(uint32_t*)(g_wpre + off + (size_t)c * chb
                 + s2 * (uint32_t)(NT / 2) * 512 + pair * 512
                 + lane * 16 + w4 * 4) = w;
}

// ---------------- A-fragment builders (single fp16, rows tl, tl+8) ----------------
__device__ __forceinline__ void build_A(
    int step, const float* __restrict__ Pp, const float* __restrict__ Xs,
    int q, int tl, uint32_t* a)
{
    const int k0 = step * 16 + q * 2;
    float zl[4], zh[4];
    #pragma unroll
    for (int e = 0; e < 4; ++e) {
        int k = k0 + (e & 1) + (e >> 1) * 8;   // {k0, k0+1, k0+8, k0+9}
        int h = k / 40;
        int m = k - h * 40;
        zl[e] = Pp[h * LDP + tl]     * Xs[m * LDP + tl];
        zh[e] = Pp[h * LDP + tl + 8] * Xs[m * LDP + tl + 8];
    }
    a[0] = packh(zl[0], zl[1]);
    a[1] = packh(zh[0], zh[1]);
    a[2] = packh(zl[2], zl[3]);
    a[3] = packh(zh[2], zh[3]);
}

// layer-0 folded: Z[k] = X[i]*X[j] via LUT
__device__ __forceinline__ void build_A0(
    int step, const float* __restrict__ Xs, const uint32_t* __restrict__ lutS,
    int q, int tl, uint32_t* a)
{
    const int k0 = step * 16 + q * 2;
    float zl[4], zh[4];
    #pragma unroll
    for (int e = 0; e < 4; ++e) {
        int k = k0 + (e & 1) + (e >> 1) * 8;
        uint32_t ij = lutS[k];
        int i = (int)(ij >> 8), j = (int)(ij & 255u);
        zl[e] = Xs[i * LDP + tl]     * Xs[j * LDP + tl];
        zh[e] = Xs[i * LDP + tl + 8] * Xs[j * LDP + tl + 8];
    }
    a[0] = packh(zl[0], zl[1]);
    a[1] = packh(zh[0], zh[1]);
    a[2] = packh(zl[2], zl[3]);
    a[3] = packh(zh[2], zh[3]);
}

// ---------------- one CIN layer: K64-staged, 1 MMA/tile ----------------
// CHB = chunk32 bytes; staged unit = 2 contiguous chunk32s (K=64).
template<int NTW, int STEPB, int CHB, bool L0>
__device__ __forceinline__ void run_layer(
    int nch64, const uint8_t* __restrict__ wpre,
    const float* __restrict__ Pp, const float* __restrict__ Xs,
    const uint32_t* __restrict__ lutS,
    const uint8_t* __restrict__ wb0, const uint8_t* __restrict__ wb1,
    uint32_t wb0u, uint32_t wb1u,
    float (&acc)[NTW][4], int tid, int lane, int q, int tl)
{
    constexpr int NP  = NTW / 2;                  // pairs per k16-step
    constexpr int CPT = (2 * CHB) / 16 / THREADS; // cp.async16 per thread (4 or 2)

    #pragma unroll
    for (int nt = 0; nt < NTW; ++nt)
        #pragma unroll
        for (int j = 0; j < 4; ++j) acc[nt][j] = 0.0f;

    __syncthreads();   // previous layer's buffer reads / P writes / LUT copy complete

    #pragma unroll
    for (int i = 0; i < CPT; ++i) {
        int e = tid + i * THREADS;
        cp_async16(wb0u + e * 16, wpre + e * 16);
    }
    CP_COMMIT();

    #pragma unroll 1
    for (int c = 0; c < nch64; ++c) {
        CP_WAIT0();
        __syncthreads();                      // chunk64 c visible; prev buffer reads done
        if (c + 1 < nch64) {
            const uint8_t* src = wpre + (size_t)(c + 1) * (2 * CHB);
            uint32_t dst = ((c + 1) & 1) ? wb1u : wb0u;
            #pragma unroll
            for (int i = 0; i < CPT; ++i) {
                int e = tid + i * THREADS;
                cp_async16(dst + e * 16, src + e * 16);
            }
        }
        CP_COMMIT();                          // overlaps with compute below
        const uint8_t* __restrict__ wb = (c & 1) ? wb1 : wb0;

        #pragma unroll
        for (int s3 = 0; s3 < 4; ++s3) {      // 4 k16-steps per staged chunk64
            uint32_t a[4];
            if (L0) build_A0(c * 4 + s3, Xs, lutS, q, tl, a);
            else    build_A (c * 4 + s3, Pp, Xs,   q, tl, a);

            const uint8_t* __restrict__ wbs =
                wb + (s3 >> 1) * CHB + (s3 & 1) * STEPB;

            #pragma unroll
            for (int p = 0; p < NP; ++p) {
                const uint4 bh = *(const uint4*)(wbs + p * 512 + lane * 16);
                mma_f16(acc[2*p  ], a, bh.x, bh.y);
                mma_f16(acc[2*p+1], a, bh.z, bh.w);
            }
        }
    }
    __syncthreads();   // all warps done reading smem before epilogue overwrites
}

// ---------------- main kernel ----------------
__global__ void __launch_bounds__(THREADS, 2)
cin_mma_kernel(const float* __restrict__ x,
               const float* __restrict__ b0, const float* __restrict__ b1,
               const float* __restrict__ b2, const float* __restrict__ wl,
               float* __restrict__ out)
{
    extern __shared__ uint8_t smraw[];
    float* Xs = (float*)(smraw + SM_XS);
    float* Ps = (float*)(smraw + SM_PS);
    uint8_t* wb0 = smraw + SM_W0;
    uint8_t* wb1 = smraw + SM_W1;
    uint32_t* lutS = (uint32_t*)(smraw + SM_LUT);
    const uint32_t wb0u = smem_u32(wb0);
    const uint32_t wb1u = smem_u32(wb1);

    const int tid  = threadIdx.x;
    const int warp = tid >> 5;        // warp == local batch (0..7)
    const int lane = tid & 31;
    const int q    = lane & 3;        // o-pair / k-pair selector
    const int rr   = lane >> 2;       // row-in-fragment
    const int tl   = warp * 16 + rr;  // rows tl, tl+8
    const int bbase = blockIdx.x * NB;

    // X tile: Xs[m][t], t = 16*local_batch + d   (40*128 elems)
    #pragma unroll 1
    for (int i = tid; i < 40 * 128; i += THREADS) {
        int m = i >> 7, t = i & 127;
        Xs[m * LDP + t] = __ldg(x + (size_t)(bbase + (t >> 4)) * 640 + m * 16 + (t & 15));
    }
    // LUT copy (ordered by run_layer's leading barrier)
    #pragma unroll 1
    for (int i = tid; i < 832; i += THREADS) lutS[i] = g_lut0[i];

    float pl = 0.0f, ph = 0.0f;       // direct partials for rows tl, tl+8

    // ========== Layer 0: folded K=832 (13 chunk64s), Z = X.X ==========
    {
        float acc[16][4];
        run_layer<16, 4096, CHB0, true>(CH0 / 2, g_wpre + OFF0, Xs, Xs, lutS,
                                        wb0, wb1, wb0u, wb1u, acc, tid, lane, q, tl);
        #pragma unroll
        for (int nt = 0; nt < 16; ++nt) {
            int o = nt * 8 + q * 2;
            float bv0 = __ldg(b0 + o), bv1 = __ldg(b0 + o + 1);
            float v0 = fmaxf(acc[nt][0] + bv0, 0.0f);
            float v1 = fmaxf(acc[nt][1] + bv1, 0.0f);
            float v2 = fmaxf(acc[nt][2] + bv0, 0.0f);
            float v3 = fmaxf(acc[nt][3] + bv1, 0.0f);
            if (nt < 8) {
                Ps[o * LDP + tl]           = v0;
                Ps[(o + 1) * LDP + tl]     = v1;
                Ps[o * LDP + tl + 8]       = v2;
                Ps[(o + 1) * LDP + tl + 8] = v3;
            } else {
                float w0v = __ldg(wl + o - 64), w1v = __ldg(wl + o - 63);
                pl += w0v * v0 + w1v * v1;
                ph += w0v * v2 + w1v * v3;
            }
        }
    }
    // ================= Layer 1: K=2560 (40 chunk64s), P = Ps =================
    {
        float acc[16][4];
        run_layer<16, 4096, CHB1, false>(CH1 / 2, g_wpre + OFF1, Ps, Xs, lutS,
                                         wb0, wb1, wb0u, wb1u, acc, tid, lane, q, tl);
        #pragma unroll
        for (int nt = 0; nt < 16; ++nt) {
            int o = nt * 8 + q * 2;
            float bv0 = __ldg(b1 + o), bv1 = __ldg(b1 + o + 1);
            float v0 = fmaxf(acc[nt][0] + bv0, 0.0f);
            float v1 = fmaxf(acc[nt][1] + bv1, 0.0f);
            float v2 = fmaxf(acc[nt][2] + bv0, 0.0f);
            float v3 = fmaxf(acc[nt][3] + bv1, 0.0f);
            if (nt < 8) {
                Ps[o * LDP + tl]           = v0;
                Ps[(o + 1) * LDP + tl]     = v1;
                Ps[o * LDP + tl + 8]       = v2;
                Ps[(o + 1) * LDP + tl + 8] = v3;
            } else {
                float w0v = __ldg(wl + o), w1v = __ldg(wl + o + 1);  // 64 + (o-64)
                pl += w0v * v0 + w1v * v1;
                ph += w0v * v2 + w1v * v3;
            }
        }
    }
    // ========= Layer 2: K=2560 (40 chunk64s), direct half only =========
    {
        float acc[8][4];
        run_layer<8, 2048, CHB2, false>(CH2 / 2, g_wpre + OFF2, Ps, Xs, lutS,
                                        wb0, wb1, wb0u, wb1u, acc, tid, lane, q, tl);
        #pragma unroll
        for (int nt = 0; nt < 8; ++nt) {
            int oc = nt * 8 + q * 2;                 // channel-in-half 0..63
            float bv0 = __ldg(b2 + 64 + oc), bv1 = __ldg(b2 + 65 + oc);
            float v0 = fmaxf(acc[nt][0] + bv0, 0.0f);
            float v1 = fmaxf(acc[nt][1] + bv1, 0.0f);
            float v2 = fmaxf(acc[nt][2] + bv0, 0.0f);
            float v3 = fmaxf(acc[nt][3] + bv1, 0.0f);
            float w0v = __ldg(wl + 128 + oc), w1v = __ldg(wl + 129 + oc);
            pl += w0v * v0 + w1v * v1;
            ph += w0v * v2 + w1v * v3;
        }
    }

    // ---- per-batch reduction: warp == batch, sum over its 16 t's ----
    float p = pl + ph;
    #pragma unroll
    for (int off = 16; off >= 1; off >>= 1)
        p += __shfl_xor_sync(0xffffffffu, p, off);
    if (lane == 0) out[bbase + warp] = p;
}

extern "C" void kernel_launch(void* const* d_in, const int* in_sizes, int n_in,
                              void* d_out, int out_size)
{
    const float* x  = (const float*)d_in[0];
    const float* w0 = (const float*)d_in[1];
    const float* b0 = (const float*)d_in[2];
    const float* w1 = (const float*)d_in[3];
    const float* b1 = (const float*)d_in[4];
    const float* w2 = (const float*)d_in[5];
    const float* b2 = (const float*)d_in[6];
    const float* wl = (const float*)d_in[7];
    float* out = (float*)d_out;

    prep_kernel<<<(PREP_TOTAL + 255) / 256, 256>>>(w0, w1, w2);

    cudaFuncSetAttribute(cin_mma_kernel,
                         cudaFuncAttributeMaxDynamicSharedMemorySize, SMEM_BYTES);
    cin_mma_kernel<<<2048 / NB, THREADS, SMEM_BYTES>>>(x, b0, b1, b2, wl, out);
}

// round 16
// speedup vs baseline: 2.8943x; 1.0950x over previous
#include <cuda_runtime.h>
#include <cuda_fp16.h>
#include <cstdint>

#define THREADS 256
#define NB 8                          // batches per CTA
#define LDP 136                       // padded smem row stride (floats)

// ---------------- smem byte layout ----------------
#define SM_XS 0                              // X : 40 x 136 f32 (t-PAIRED layout)
#define SM_PS (40*LDP*4)                     // P : 64 x 136 f32 (t-PAIRED layout)
#define SM_W0 (SM_PS + 64*LDP*4)             // W chunk64 buf0 (16KB max)
#define SM_W1 (SM_W0 + 16384)                // W chunk64 buf1 (16KB max)
#define SM_LUT (SM_W1 + 16384)               // layer-0 fold LUT: 832 u32
#define SMEM_BYTES (SM_LUT + 832*4)          // 92,672 bytes -> 2 CTAs/SM

// t-paired layout: within each warp's 16-column block, global row t and t+8
// sit at adjacent floats: offset = (t&0x70) + (t&7)*2 + ((t>>3)&1)

// ---------------- prepped-W global scratch (fp16 single) ----------------
#define NT0 16
#define NT1 16
#define NT2 8
#define CH0 26               // layer 0 FOLDED: K=820 -> 832 = 26 chunk32s
#define CH1 80
#define CH2 80
#define CHB0 (NT0*512)       // 8192 B per chunk32
#define CHB1 (NT1*512)       // 8192 B
#define CHB2 (NT2*512)       // 4096 B
#define OFF0 0u
#define OFF1 (CH0*CHB0)                  // 212992
#define OFF2 (OFF1 + CH1*CHB1)           // 868352
#define WPRE_BYTES (OFF2 + CH2*CHB2)     // 1195712

__device__ __align__(16) uint8_t g_wpre[WPRE_BYTES];
__device__ uint32_t g_lut0[832];             // packed (i<<8)|j per folded k

// ---------------- helpers ----------------
__device__ __forceinline__ uint32_t packh(float lo, float hi) {
    __half2 h = __floats2half2_rn(lo, hi);
    return *(uint32_t*)&h;
}
__device__ __forceinline__ void mma_f16(float* c, const uint32_t* a,
                                        uint32_t b0, uint32_t b1) {
    asm volatile(
        "mma.sync.aligned.m16n8k16.row.col.f32.f16.f16.f32 "
        "{%0,%1,%2,%3}, {%4,%5,%6,%7}, {%8,%9}, {%0,%1,%2,%3};"
        : "+f"(c[0]), "+f"(c[1]), "+f"(c[2]), "+f"(c[3])
        : "r"(a[0]), "r"(a[1]), "r"(a[2]), "r"(a[3]), "r"(b0), "r"(b1));
}
__device__ __forceinline__ uint32_t smem_u32(const void* p) {
    uint32_t a;
    asm("{ .reg .u64 t; cvta.to.shared.u64 t, %1; cvt.u32.u64 %0, t; }" : "=r"(a) : "l"(p));
    return a;
}
__device__ __forceinline__ void cp_async16(uint32_t dst, const void* src) {
    asm volatile("cp.async.cg.shared.global [%0], [%1], 16;" :: "r"(dst), "l"(src));
}
#define CP_COMMIT() asm volatile("cp.async.commit_group;" ::: "memory")
#define CP_WAIT0()  asm volatile("cp.async.wait_group 0;" ::: "memory")

// folded-k -> (i,j), i<=j, row i holds (40-i) entries
__device__ __forceinline__ void fold_ij(int k, int& i, int& j) {
    i = 0; int rem = k;
    while (rem >= 40 - i) { rem -= (40 - i); ++i; }
    j = i + rem;
}
__device__ __forceinline__ float foldedW0(const float* __restrict__ w0, int o, int k) {
    if (k >= 820) return 0.0f;
    int i, j; fold_ij(k, i, j);
    float v = __ldg(w0 + (size_t)o * 1600 + i * 40 + j);
    if (i != j) v += __ldg(w0 + (size_t)o * 1600 + j * 40 + i);
    return v;
}

// ---------------- prep: fold L0 + fp16-round all W into paired blocks ----------------
#define WORDS0 (CH0*NT0*128)   // 53248
#define WORDS1 (CH1*NT1*128)   // 163840
#define WORDS2 (CH2*NT2*128)   // 81920
#define PREP_TOTAL (WORDS0 + WORDS1 + WORDS2 + 832)

__global__ void prep_kernel(const float* __restrict__ w0,
                            const float* __restrict__ w1,
                            const float* __restrict__ w2)
{
    int idx = blockIdx.x * blockDim.x + threadIdx.x;
    if (idx >= PREP_TOTAL) return;
    if (idx >= WORDS0 + WORDS1 + WORDS2) {          // LUT fill
        int k = idx - (WORDS0 + WORDS1 + WORDS2);
        uint32_t v = 0;
        if (k < 820) { int i, j; fold_ij(k, i, j); v = ((uint32_t)i << 8) | (uint32_t)j; }
        g_lut0[k] = v;
        return;
    }
    int lay, NT, li; uint32_t off, chb;
    const float* src = nullptr; int ld = 0, rowBase = 0;
    if (idx < WORDS0)                  { lay=0; NT=NT0; off=OFF0; chb=CHB0; li=idx; }
    else if (idx < WORDS0+WORDS1)      { lay=1; src=w1; NT=NT1; ld=2560; rowBase=0;  off=OFF1; chb=CHB1; li=idx-WORDS0; }
    else                               { lay=2; src=w2; NT=NT2; ld=2560; rowBase=64; off=OFF2; chb=CHB2; li=idx-WORDS0-WORDS1; }

    int perChunk = NT * 128;                  // b32 words per chunk32
    int c    = li / perChunk;
    int r    = li - c * perChunk;
    int half = NT * 64;                       // words per k16-step
    int s2   = r / half;
    int r2   = r - s2 * half;
    int pair = r2 >> 7;                       // 128 words per pair block
    int r3   = r2 & 127;
    int lane = r3 >> 2;
    int w4   = r3 & 3;                        // word within 16B
    int tile = pair * 2 + (w4 >> 1);
    int wsel = w4 & 1;                        // b0 (k+0..1) or b1 (k+8..9)

    int o = tile * 8 + (lane >> 2);
    int k = c * 32 + s2 * 16 + (lane & 3) * 2 + wsel * 8;
    float a, b;
    if (lay == 0) {
        a = foldedW0(w0, o, k);
        b = foldedW0(w0, o, k + 1);
    } else {
        a = __ldg(src + (size_t)(rowBase + o) * ld + k);
        b = __ldg(src + (size_t)(rowBase + o) * ld + k + 1);
    }
    uint32_t w = packh(a, b);                 // fp16 round-nearest, low half = k

    *(uint32_t*)(g_wpre + off + (size_t)c * chb
                 + s2 * (uint32_t)(NT / 2) * 512 + pair * 512
                 + lane * 16 + w4 * 4) = w;
}

// ---------------- A-fragment builders (paired loads; rows tl, tl+8 in .x/.y) ----------------
// pb = warp*16 + rr*2 : float2 at [row*LDP + pb] = {val(tl), val(tl+8)}
__device__ __forceinline__ void build_A(
    int step, const float* __restrict__ Pp, const float* __restrict__ Xs,
    int q, int pb, uint32_t* a)
{
    const int k0 = step * 16 + q * 2;
    const int h0 = k0 / 40,       m0 = k0 - h0 * 40;        // (k0,k0+1) share h0; m0 even
    const int k8 = k0 + 8;
    const int h8 = k8 / 40,       m8 = k8 - h8 * 40;        // (k0+8,k0+9) share h8; m8 even
    const float2 P0 = *(const float2*)(Pp + h0 * LDP + pb);
    const float2 P8 = *(const float2*)(Pp + h8 * LDP + pb);
    const float2 X0 = *(const float2*)(Xs + m0 * LDP + pb);
    const float2 X1 = *(const float2*)(Xs + (m0 + 1) * LDP + pb);
    const float2 X8 = *(const float2*)(Xs + m8 * LDP + pb);
    const float2 X9 = *(const float2*)(Xs + (m8 + 1) * LDP + pb);
    a[0] = packh(P0.x * X0.x, P0.x * X1.x);   // (zl0, zl1) row tl
    a[1] = packh(P0.y * X0.y, P0.y * X1.y);   // (zh0, zh1) row tl+8
    a[2] = packh(P8.x * X8.x, P8.x * X9.x);
    a[3] = packh(P8.y * X8.y, P8.y * X9.y);
}

// layer-0 folded: Z[k] = X[i]*X[j] via LUT (paired loads)
__device__ __forceinline__ void build_A0(
    int step, const float* __restrict__ Xs, const uint32_t* __restrict__ lutS,
    int q, int pb, uint32_t* a)
{
    const int k0 = step * 16 + q * 2;                       // even -> 8B aligned
    const uint2 l01 = *(const uint2*)(lutS + k0);
    const uint2 l89 = *(const uint2*)(lutS + k0 + 8);
    const uint32_t ij[4] = { l01.x, l01.y, l89.x, l89.y };
    float zl[4], zh[4];
    #pragma unroll
    for (int e = 0; e < 4; ++e) {
        int i = (int)(ij[e] >> 8), j = (int)(ij[e] & 255u);
        const float2 Xi = *(const float2*)(Xs + i * LDP + pb);
        const float2 Xj = *(const float2*)(Xs + j * LDP + pb);
        zl[e] = Xi.x * Xj.x;
        zh[e] = Xi.y * Xj.y;
    }
    a[0] = packh(zl[0], zl[1]);
    a[1] = packh(zh[0], zh[1]);
    a[2] = packh(zl[2], zl[3]);
    a[3] = packh(zh[2], zh[3]);
}

// ---------------- one CIN layer: K64-staged, 1 MMA/tile ----------------
template<int NTW, int STEPB, int CHB, bool L0>
__device__ __forceinline__ void run_layer(
    int nch64, const uint8_t* __restrict__ wpre,
    const float* __restrict__ Pp, const float* __restrict__ Xs,
    const uint32_t* __restrict__ lutS,
    const uint8_t* __restrict__ wb0, const uint8_t* __restrict__ wb1,
    uint32_t wb0u, uint32_t wb1u,
    float (&acc)[NTW][4], int tid, int lane, int q, int pb)
{
    constexpr int NP  = NTW / 2;                  // pairs per k16-step
    constexpr int CPT = (2 * CHB) / 16 / THREADS; // cp.async16 per thread (4 or 2)

    #pragma unroll
    for (int nt = 0; nt < NTW; ++nt)
        #pragma unroll
        for (int j = 0; j < 4; ++j) acc[nt][j] = 0.0f;

    __syncthreads();   // previous layer's buffer reads / P writes / LUT copy complete

    #pragma unroll
    for (int i = 0; i < CPT; ++i) {
        int e = tid + i * THREADS;
        cp_async16(wb0u + e * 16, wpre + e * 16);
    }
    CP_COMMIT();

    #pragma unroll 1
    for (int c = 0; c < nch64; ++c) {
        CP_WAIT0();
        __syncthreads();                      // chunk64 c visible; prev buffer reads done
        if (c + 1 < nch64) {
            const uint8_t* src = wpre + (size_t)(c + 1) * (2 * CHB);
            uint32_t dst = ((c + 1) & 1) ? wb1u : wb0u;
            #pragma unroll
            for (int i = 0; i < CPT; ++i) {
                int e = tid + i * THREADS;
                cp_async16(dst + e * 16, src + e * 16);
            }
        }
        CP_COMMIT();                          // overlaps with compute below
        const uint8_t* __restrict__ wb = (c & 1) ? wb1 : wb0;

        #pragma unroll
        for (int s3 = 0; s3 < 4; ++s3) {      // 4 k16-steps per staged chunk64
            uint32_t a[4];
            if (L0) build_A0(c * 4 + s3, Xs, lutS, q, pb, a);
            else    build_A (c * 4 + s3, Pp, Xs,   q, pb, a);

            const uint8_t* __restrict__ wbs =
                wb + (s3 >> 1) * CHB + (s3 & 1) * STEPB;

            #pragma unroll
            for (int p = 0; p < NP; ++p) {
                const uint4 bh = *(const uint4*)(wbs + p * 512 + lane * 16);
                mma_f16(acc[2*p  ], a, bh.x, bh.y);
                mma_f16(acc[2*p+1], a, bh.z, bh.w);
            }
        }
    }
    __syncthreads();   // all warps done reading smem before epilogue overwrites
}

// ---------------- main kernel ----------------
__global__ void __launch_bounds__(THREADS, 2)
cin_mma_kernel(const float* __restrict__ x,
               const float* __restrict__ b0, const float* __restrict__ b1,
               const float* __restrict__ b2, const float* __restrict__ wl,
               float* __restrict__ out)
{
    extern __shared__ uint8_t smraw[];
    float* Xs = (float*)(smraw + SM_XS);
    float* Ps = (float*)(smraw + SM_PS);
    uint8_t* wb0 = smraw + SM_W0;
    uint8_t* wb1 = smraw + SM_W1;
    uint32_t* lutS = (uint32_t*)(smraw + SM_LUT);
    const uint32_t wb0u = smem_u32(wb0);
    const uint32_t wb1u = smem_u32(wb1);

    const int tid  = threadIdx.x;
    const int warp = tid >> 5;        // warp == local batch (0..7)
    const int lane = tid & 31;
    const int q    = lane & 3;        // o-pair / k-pair selector
    const int rr   = lane >> 2;       // row-in-fragment
    const int pb   = warp * 16 + rr * 2;  // paired base: {tl, tl+8}
    const int bbase = blockIdx.x * NB;

    // X tile into t-PAIRED layout: offset = (t&0x70) + (t&7)*2 + ((t>>3)&1)
    #pragma unroll 1
    for (int i = tid; i < 40 * 128; i += THREADS) {
        int m = i >> 7, t = i & 127;
        int pt = (t & 0x70) + ((t & 7) << 1) + ((t >> 3) & 1);
        Xs[m * LDP + pt] = __ldg(x + (size_t)(bbase + (t >> 4)) * 640 + m * 16 + (t & 15));
    }
    // LUT copy (ordered by run_layer's leading barrier)
    #pragma unroll 1
    for (int i = tid; i < 832; i += THREADS) lutS[i] = g_lut0[i];

    float pl = 0.0f, ph = 0.0f;       // direct partials for rows tl, tl+8

    // ========== Layer 0: folded K=832 (13 chunk64s), Z = X.X ==========
    {
        float acc[16][4];
        run_layer<16, 4096, CHB0, true>(CH0 / 2, g_wpre + OFF0, Xs, Xs, lutS,
                                        wb0, wb1, wb0u, wb1u, acc, tid, lane, q, pb);
        #pragma unroll
        for (int nt = 0; nt < 16; ++nt) {
            int o = nt * 8 + q * 2;
            float bv0 = __ldg(b0 + o), bv1 = __ldg(b0 + o + 1);
            float v0 = fmaxf(acc[nt][0] + bv0, 0.0f);
            float v1 = fmaxf(acc[nt][1] + bv1, 0.0f);
            float v2 = fmaxf(acc[nt][2] + bv0, 0.0f);
            float v3 = fmaxf(acc[nt][3] + bv1, 0.0f);
            if (nt < 8) {
                *(float2*)(Ps + o * LDP + pb)       = make_float2(v0, v2);
                *(float2*)(Ps + (o + 1) * LDP + pb) = make_float2(v1, v3);
            } else {
                float w0v = __ldg(wl + o - 64), w1v = __ldg(wl + o - 63);
                pl += w0v * v0 + w1v * v1;
                ph += w0v * v2 + w1v * v3;
            }
        }
    }
    // ================= Layer 1: K=2560 (40 chunk64s), P = Ps =================
    {
        float acc[16][4];
        run_layer<16, 4096, CHB1, false>(CH1 / 2, g_wpre + OFF1, Ps, Xs, lutS,
                                         wb0, wb1, wb0u, wb1u, acc, tid, lane, q, pb);
        #pragma unroll
        for (int nt = 0; nt < 16; ++nt) {
            int o = nt * 8 + q * 2;
            float bv0 = __ldg(b1 + o), bv1 = __ldg(b1 + o + 1);
            float v0 = fmaxf(acc[nt][0] + bv0, 0.0f);
            float v1 = fmaxf(acc[nt][1] + bv1, 0.0f);
            float v2 = fmaxf(acc[nt][2] + bv0, 0.0f);
            float v3 = fmaxf(acc[nt][3] + bv1, 0.0f);
            if (nt < 8) {
                *(float2*)(Ps + o * LDP + pb)       = make_float2(v0, v2);
                *(float2*)(Ps + (o + 1) * LDP + pb) = make_float2(v1, v3);
            } else {
                float w0v = __ldg(wl + o), w1v = __ldg(wl + o + 1);  // 64 + (o-64)
                pl += w0v * v0 + w1v * v1;
                ph += w0v * v2 + w1v * v3;
            }
        }
    }
    // ========= Layer 2: K=2560 (40 chunk64s), direct half only =========
    {
        float acc[8][4];
        run_layer<8, 2048, CHB2, false>(CH2 / 2, g_wpre + OFF2, Ps, Xs, lutS,
                                        wb0, wb1, wb0u, wb1u, acc, tid, lane, q, pb);
        #pragma unroll
        for (int nt = 0; nt < 8; ++nt) {
            int oc = nt * 8 + q * 2;                 // channel-in-half 0..63
            float bv0 = __ldg(b2 + 64 + oc), bv1 = __ldg(b2 + 65 + oc);
            float v0 = fmaxf(acc[nt][0] + bv0, 0.0f);
            float v1 = fmaxf(acc[nt][1] + bv1, 0.0f);
            float v2 = fmaxf(acc[nt][2] + bv0, 0.0f);
            float v3 = fmaxf(acc[nt][3] + bv1, 0.0f);
            float w0v = __ldg(wl + 128 + oc), w1v = __ldg(wl + 129 + oc);
            pl += w0v * v0 + w1v * v1;
            ph += w0v * v2 + w1v * v3;
        }
    }

    // ---- per-batch reduction: warp == batch, sum over its 16 t's ----
    float p = pl + ph;
    #pragma unroll
    for (int off = 16; off >= 1; off >>= 1)
        p += __shfl_xor_sync(0xffffffffu, p, off);
    if (lane == 0) out[bbase + warp] = p;
}

extern "C" void kernel_launch(void* const* d_in, const int* in_sizes, int n_in,
                              void* d_out, int out_size)
{
    const float* x  = (const float*)d_in[0];
    const float* w0 = (const float*)d_in[1];
    const float* b0 = (const float*)d_in[2];
    const float* w1 = (const float*)d_in[3];
    const float* b1 = (const float*)d_in[4];
    const float* w2 = (const float*)d_in[5];
    const float* b2 = (const float*)d_in[6];
    const float* wl = (const float*)d_in[7];
    float* out = (float*)d_out;

    prep_kernel<<<(PREP_TOTAL + 255) / 256, 256>>>(w0, w1, w2);

    cudaFuncSetAttribute(cin_mma_kernel,
                         cudaFuncAttributeMaxDynamicSharedMemorySize, SMEM_BYTES);
    cin_mma_kernel<<<2048 / NB, THREADS, SMEM_BYTES>>>(x, b0, b1, b2, wl, out);
}

// round 17
// speedup vs baseline: 3.3932x; 1.1724x over previous
#include <cuda_runtime.h>
#include <cuda_fp16.h>
#include <cstdint>

#define THREADS 256
#define NB 8                          // batches per CTA
#define LDPH 136                      // padded smem row stride (halves)

// ---------------- smem byte layout ----------------
#define SM_XS 0                              // X : 40 x 136 half (t-paired)
#define SM_PS (40*LDPH*2)                    // P : 64 x 136 half (t-paired)  -> 10880
#define SM_W0 (SM_PS + 64*LDPH*2)            // W chunk64 buf0 (16KB)         -> 28288
#define SM_W1 (SM_W0 + 16384)
#define SM_LUT (SM_W1 + 16384)               // layer-0 fold LUT: 832 u32
#define SMEM_BYTES (SM_LUT + 832*4)          // 64,384 bytes -> 2 CTAs/SM

// t-paired layout (half units): offset = (t&0x70) + (t&7)*2 + ((t>>3)&1)

// ---------------- prepped-W global scratch (fp16 single) ----------------
#define NT0 16
#define NT1 16
#define NT2 8
#define CH0 26               // layer 0 FOLDED: K=820 -> 832 = 26 chunk32s
#define CH1 80
#define CH2 80
#define CHB0 (NT0*512)       // 8192 B per chunk32
#define CHB1 (NT1*512)
#define CHB2 (NT2*512)       // 4096 B
#define OFF0 0u
#define OFF1 (CH0*CHB0)
#define OFF2 (OFF1 + CH1*CHB1)
#define WPRE_BYTES (OFF2 + CH2*CHB2)

__device__ __align__(16) uint8_t g_wpre[WPRE_BYTES];
__device__ uint32_t g_lut0[832];             // packed (i<<8)|j per folded k

// ---------------- helpers ----------------
__device__ __forceinline__ uint32_t packh(float lo, float hi) {
    __half2 h = __floats2half2_rn(lo, hi);
    return *(uint32_t*)&h;
}
__device__ __forceinline__ uint32_t hmul2u(uint32_t a, uint32_t b) {
    __half2 r = __hmul2(*(__half2*)&a, *(__half2*)&b);
    return *(uint32_t*)&r;
}
__device__ __forceinline__ uint32_t prmt(uint32_t a, uint32_t b, uint32_t sel) {
    uint32_t r;
    asm("prmt.b32 %0, %1, %2, %3;" : "=r"(r) : "r"(a), "r"(b), "r"(sel));
    return r;
}
__device__ __forceinline__ void mma_f16(float* c, const uint32_t* a,
                                        uint32_t b0, uint32_t b1) {
    asm volatile(
        "mma.sync.aligned.m16n8k16.row.col.f32.f16.f16.f32 "
        "{%0,%1,%2,%3}, {%4,%5,%6,%7}, {%8,%9}, {%0,%1,%2,%3};"
        : "+f"(c[0]), "+f"(c[1]), "+f"(c[2]), "+f"(c[3])
        : "r"(a[0]), "r"(a[1]), "r"(a[2]), "r"(a[3]), "r"(b0), "r"(b1));
}
__device__ __forceinline__ uint32_t smem_u32(const void* p) {
    uint32_t a;
    asm("{ .reg .u64 t; cvta.to.shared.u64 t, %1; cvt.u32.u64 %0, t; }" : "=r"(a) : "l"(p));
    return a;
}
__device__ __forceinline__ void cp_async16(uint32_t dst, const void* src) {
    asm volatile("cp.async.cg.shared.global [%0], [%1], 16;" :: "r"(dst), "l"(src));
}
#define CP_COMMIT() asm volatile("cp.async.commit_group;" ::: "memory")
#define CP_WAIT0()  asm volatile("cp.async.wait_group 0;" ::: "memory")

// folded-k -> (i,j), i<=j
__device__ __forceinline__ void fold_ij(int k, int& i, int& j) {
    i = 0; int rem = k;
    while (rem >= 40 - i) { rem -= (40 - i); ++i; }
    j = i + rem;
}
__device__ __forceinline__ float foldedW0(const float* __restrict__ w0, int o, int k) {
    if (k >= 820) return 0.0f;
    int i, j; fold_ij(k, i, j);
    float v = __ldg(w0 + (size_t)o * 1600 + i * 40 + j);
    if (i != j) v += __ldg(w0 + (size_t)o * 1600 + j * 40 + i);
    return v;
}

// ---------------- prep (unchanged layout from R16) ----------------
#define WORDS0 (CH0*NT0*128)
#define WORDS1 (CH1*NT1*128)
#define WORDS2 (CH2*NT2*128)
#define PREP_TOTAL (WORDS0 + WORDS1 + WORDS2 + 832)

__global__ void prep_kernel(const float* __restrict__ w0,
                            const float* __restrict__ w1,
                            const float* __restrict__ w2)
{
    int idx = blockIdx.x * blockDim.x + threadIdx.x;
    if (idx >= PREP_TOTAL) return;
    if (idx >= WORDS0 + WORDS1 + WORDS2) {
        int k = idx - (WORDS0 + WORDS1 + WORDS2);
        uint32_t v = 0;
        if (k < 820) { int i, j; fold_ij(k, i, j); v = ((uint32_t)i << 8) | (uint32_t)j; }
        g_lut0[k] = v;
        return;
    }
    int lay, NT, li; uint32_t off, chb;
    const float* src = nullptr; int ld = 0, rowBase = 0;
    if (idx < WORDS0)                  { lay=0; NT=NT0; off=OFF0; chb=CHB0; li=idx; }
    else if (idx < WORDS0+WORDS1)      { lay=1; src=w1; NT=NT1; ld=2560; rowBase=0;  off=OFF1; chb=CHB1; li=idx-WORDS0; }
    else                               { lay=2; src=w2; NT=NT2; ld=2560; rowBase=64; off=OFF2; chb=CHB2; li=idx-WORDS0-WORDS1; }

    int perChunk = NT * 128;
    int c    = li / perChunk;
    int r    = li - c * perChunk;
    int half = NT * 64;
    int s2   = r / half;
    int r2   = r - s2 * half;
    int pair = r2 >> 7;
    int r3   = r2 & 127;
    int lane = r3 >> 2;
    int w4   = r3 & 3;
    int tile = pair * 2 + (w4 >> 1);
    int wsel = w4 & 1;

    int o = tile * 8 + (lane >> 2);
    int k = c * 32 + s2 * 16 + (lane & 3) * 2 + wsel * 8;
    float a, b;
    if (lay == 0) {
        a = foldedW0(w0, o, k);
        b = foldedW0(w0, o, k + 1);
    } else {
        a = __ldg(src + (size_t)(rowBase + o) * ld + k);
        b = __ldg(src + (size_t)(rowBase + o) * ld + k + 1);
    }
    uint32_t w = packh(a, b);

    *(uint32_t*)(g_wpre + off + (size_t)c * chb
                 + s2 * (uint32_t)(NT / 2) * 512 + pair * 512
                 + lane * 16 + w4 * 4) = w;
}

// ---------------- A-builders: half2 paired loads, HMUL2 + PRMT repack ----------------
// pb (halves): {t, t+8} pair base for this thread's fragment rows.
__device__ __forceinline__ void build_A(
    int step, const __half* __restrict__ Pp, const __half* __restrict__ Xs,
    int q, int pb, uint32_t* a)
{
    const int k0 = step * 16 + q * 2;
    const int h0 = k0 / 40, m0 = k0 - h0 * 40;   // m0 even; (k0,k0+1) share h0
    const int k8 = k0 + 8;
    const int h8 = k8 / 40, m8 = k8 - h8 * 40;
    const uint32_t P0 = *(const uint32_t*)(Pp + h0 * LDPH + pb);
    const uint32_t P8 = *(const uint32_t*)(Pp + h8 * LDPH + pb);
    const uint32_t X0 = *(const uint32_t*)(Xs + m0 * LDPH + pb);
    const uint32_t X1 = *(const uint32_t*)(Xs + (m0 + 1) * LDPH + pb);
    const uint32_t X8 = *(const uint32_t*)(Xs + m8 * LDPH + pb);
    const uint32_t X9 = *(const uint32_t*)(Xs + (m8 + 1) * LDPH + pb);
    const uint32_t z0 = hmul2u(P0, X0);          // {z_k0(t), z_k0(t+8)}
    const uint32_t z1 = hmul2u(P0, X1);
    const uint32_t z8 = hmul2u(P8, X8);
    const uint32_t z9 = hmul2u(P8, X9);
    a[0] = prmt(z0, z1, 0x5410);                 // {z_k0(t),   z_k1(t)}
    a[1] = prmt(z0, z1, 0x7632);                 // {z_k0(t+8), z_k1(t+8)}
    a[2] = prmt(z8, z9, 0x5410);
    a[3] = prmt(z8, z9, 0x7632);
}

__device__ __forceinline__ void build_A0(
    int step, const __half* __restrict__ Xs, const uint32_t* __restrict__ lutS,
    int q, int pb, uint32_t* a)
{
    const int k0 = step * 16 + q * 2;            // even -> uint2 8B aligned
    const uint2 l01 = *(const uint2*)(lutS + k0);
    const uint2 l89 = *(const uint2*)(lutS + k0 + 8);
    const uint32_t ij[4] = { l01.x, l01.y, l89.x, l89.y };
    uint32_t z[4];
    #pragma unroll
    for (int e = 0; e < 4; ++e) {
        int i = (int)(ij[e] >> 8), j = (int)(ij[e] & 255u);
        const uint32_t Xi = *(const uint32_t*)(Xs + i * LDPH + pb);
        const uint32_t Xj = *(const uint32_t*)(Xs + j * LDPH + pb);
        z[e] = hmul2u(Xi, Xj);
    }
    a[0] = prmt(z[0], z[1], 0x5410);
    a[1] = prmt(z[0], z[1], 0x7632);
    a[2] = prmt(z[2], z[3], 0x5410);
    a[3] = prmt(z[2], z[3], 0x7632);
}

// ---------------- one CIN layer: warp = (t32 x o-half), 2 m-tiles share B ----------------
template<int NTW, int STEPB, int CHB, bool L0>
__device__ __forceinline__ void run_layer(
    int nch64, const uint8_t* __restrict__ wpre,
    const __half* __restrict__ Pp, const __half* __restrict__ Xs,
    const uint32_t* __restrict__ lutS,
    const uint8_t* __restrict__ wb0, const uint8_t* __restrict__ wb1,
    uint32_t wb0u, uint32_t wb1u, int pairBase,
    float (&acc)[2][NTW][4], int tid, int lane, int q, int pb)
{
    constexpr int NP  = NTW / 2;                  // B pair-loads per step
    constexpr int CPT = (2 * CHB) / 16 / THREADS;

    #pragma unroll
    for (int mt = 0; mt < 2; ++mt)
        #pragma unroll
        for (int nt = 0; nt < NTW; ++nt)
            #pragma unroll
            for (int j = 0; j < 4; ++j) acc[mt][nt][j] = 0.0f;

    __syncthreads();   // prev layer's buffer reads / P writes / LUT copy complete

    #pragma unroll
    for (int i = 0; i < CPT; ++i) {
        int e = tid + i * THREADS;
        cp_async16(wb0u + e * 16, wpre + e * 16);
    }
    CP_COMMIT();

    #pragma unroll 1
    for (int c = 0; c < nch64; ++c) {
        CP_WAIT0();
        __syncthreads();
        if (c + 1 < nch64) {
            const uint8_t* src = wpre + (size_t)(c + 1) * (2 * CHB);
            uint32_t dst = ((c + 1) & 1) ? wb1u : wb0u;
            #pragma unroll
            for (int i = 0; i < CPT; ++i) {
                int e = tid + i * THREADS;
                cp_async16(dst + e * 16, src + e * 16);
            }
        }
        CP_COMMIT();
        const uint8_t* __restrict__ wb = (c & 1) ? wb1 : wb0;

        #pragma unroll
        for (int s3 = 0; s3 < 4; ++s3) {
            uint32_t a0[4], a1[4];
            if (L0) { build_A0(c * 4 + s3, Xs, lutS, q, pb, a0);
                      build_A0(c * 4 + s3, Xs, lutS, q, pb + 16, a1); }
            else    { build_A (c * 4 + s3, Pp, Xs,   q, pb, a0);
                      build_A (c * 4 + s3, Pp, Xs,   q, pb + 16, a1); }

            const uint8_t* __restrict__ wbs =
                wb + (s3 >> 1) * CHB + (s3 & 1) * STEPB + pairBase;

            #pragma unroll
            for (int p = 0; p < NP; ++p) {
                const uint4 bh = *(const uint4*)(wbs + p * 512 + lane * 16);
                mma_f16(acc[0][2*p  ], a0, bh.x, bh.y);
                mma_f16(acc[0][2*p+1], a0, bh.z, bh.w);
                mma_f16(acc[1][2*p  ], a1, bh.x, bh.y);
                mma_f16(acc[1][2*p+1], a1, bh.z, bh.w);
            }
        }
    }
    __syncthreads();   // all warps done reading smem before epilogue overwrites
}

// ---------------- main kernel ----------------
__global__ void __launch_bounds__(THREADS, 2)
cin_mma_kernel(const float* __restrict__ x,
               const float* __restrict__ b0, const float* __restrict__ b1,
               const float* __restrict__ b2, const float* __restrict__ wl,
               float* __restrict__ out)
{
    extern __shared__ uint8_t smraw[];
    __half* Xs = (__half*)(smraw + SM_XS);
    __half* Ps = (__half*)(smraw + SM_PS);
    uint8_t* wb0 = smraw + SM_W0;
    uint8_t* wb1 = smraw + SM_W1;
    uint32_t* lutS = (uint32_t*)(smraw + SM_LUT);
    const uint32_t wb0u = smem_u32(wb0);
    const uint32_t wb1u = smem_u32(wb1);

    const int tid   = threadIdx.x;
    const int warp  = tid >> 5;
    const int lane  = tid & 31;
    const int q     = lane & 3;
    const int rr    = lane >> 2;
    const int warpT = warp & 3;          // t-group: rows warpT*32..+31 (2 batches)
    const int warpO = warp >> 2;         // o-half: 0 -> o 0..63, 1 -> o 64..127
    const int pb    = warpT * 32 + rr * 2;   // paired base (halves); m-tile1 at +16
    const int bbase = blockIdx.x * NB;

    // X tile into t-paired fp16 layout
    #pragma unroll 1
    for (int i = tid; i < 40 * 128; i += THREADS) {
        int m = i >> 7, t = i & 127;
        int pt = (t & 0x70) + ((t & 7) << 1) + ((t >> 3) & 1);
        Xs[m * LDPH + pt] =
            __float2half_rn(__ldg(x + (size_t)(bbase + (t >> 4)) * 640 + m * 16 + (t & 15)));
    }
    #pragma unroll 1
    for (int i = tid; i < 832; i += THREADS) lutS[i] = g_lut0[i];

    float pA = 0.0f, pB = 0.0f;   // direct partials for batch 2*warpT, 2*warpT+1

    // ========== Layer 0: folded K=832 (13 chunk64s), Z = X.X ==========
    {
        float acc[2][8][4];
        run_layer<8, 4096, CHB0, true>(CH0 / 2, g_wpre + OFF0, Ps, Xs, lutS,
                                       wb0, wb1, wb0u, wb1u, warpO * 2048,
                                       acc, tid, lane, q, pb);
        #pragma unroll
        for (int nt = 0; nt < 8; ++nt) {
            int o = warpO * 64 + nt * 8 + q * 2;
            float bv0 = __ldg(b0 + o), bv1 = __ldg(b0 + o + 1);
            #pragma unroll
            for (int mt = 0; mt < 2; ++mt) {
                float v0 = fmaxf(acc[mt][nt][0] + bv0, 0.0f);
                float v1 = fmaxf(acc[mt][nt][1] + bv1, 0.0f);
                float v2 = fmaxf(acc[mt][nt][2] + bv0, 0.0f);
                float v3 = fmaxf(acc[mt][nt][3] + bv1, 0.0f);
                if (warpO == 0) {
                    int pbm = pb + mt * 16;
                    *(uint32_t*)(Ps + o * LDPH + pbm)       = packh(v0, v2);
                    *(uint32_t*)(Ps + (o + 1) * LDPH + pbm) = packh(v1, v3);
                } else {
                    float w0v = __ldg(wl + o - 64), w1v = __ldg(wl + o - 63);
                    float s = w0v * (v0 + v2) + w1v * (v1 + v3);
                    if (mt == 0) pA += s; else pB += s;
                }
            }
        }
    }
    // ================= Layer 1: K=2560 (40 chunk64s), P = Ps =================
    {
        float acc[2][8][4];
        run_layer<8, 4096, CHB1, false>(CH1 / 2, g_wpre + OFF1, Ps, Xs, lutS,
                                        wb0, wb1, wb0u, wb1u, warpO * 2048,
                                        acc, tid, lane, q, pb);
        #pragma unroll
        for (int nt = 0; nt < 8; ++nt) {
            int o = warpO * 64 + nt * 8 + q * 2;
            float bv0 = __ldg(b1 + o), bv1 = __ldg(b1 + o + 1);
            #pragma unroll
            for (int mt = 0; mt < 2; ++mt) {
                float v0 = fmaxf(acc[mt][nt][0] + bv0, 0.0f);
                float v1 = fmaxf(acc[mt][nt][1] + bv1, 0.0f);
                float v2 = fmaxf(acc[mt][nt][2] + bv0, 0.0f);
                float v3 = fmaxf(acc[mt][nt][3] + bv1, 0.0f);
                if (warpO == 0) {
                    int pbm = pb + mt * 16;
                    *(uint32_t*)(Ps + o * LDPH + pbm)       = packh(v0, v2);
                    *(uint32_t*)(Ps + (o + 1) * LDPH + pbm) = packh(v1, v3);
                } else {
                    float w0v = __ldg(wl + o), w1v = __ldg(wl + o + 1);
                    float s = w0v * (v0 + v2) + w1v * (v1 + v3);
                    if (mt == 0) pA += s; else pB += s;
                }
            }
        }
    }
    // ========= Layer 2: K=2560 (40 chunk64s), direct half only (o-split) =========
    {
        float acc[2][4][4];
        run_layer<4, 2048, CHB2, false>(CH2 / 2, g_wpre + OFF2, Ps, Xs, lutS,
                                        wb0, wb1, wb0u, wb1u, warpO * 1024,
                                        acc, tid, lane, q, pb);
        #pragma unroll
        for (int nt = 0; nt < 4; ++nt) {
            int oc = warpO * 32 + nt * 8 + q * 2;
            float bv0 = __ldg(b2 + 64 + oc), bv1 = __ldg(b2 + 65 + oc);
            float w0v = __ldg(wl + 128 + oc), w1v = __ldg(wl + 129 + oc);
            #pragma unroll
            for (int mt = 0; mt < 2; ++mt) {
                float v0 = fmaxf(acc[mt][nt][0] + bv0, 0.0f);
                float v1 = fmaxf(acc[mt][nt][1] + bv1, 0.0f);
                float v2 = fmaxf(acc[mt][nt][2] + bv0, 0.0f);
                float v3 = fmaxf(acc[mt][nt][3] + bv1, 0.0f);
                float s = w0v * (v0 + v2) + w1v * (v1 + v3);
                if (mt == 0) pA += s; else pB += s;
            }
        }
    }

    // ---- reduce to per-batch outputs (W buffers dead after final barrier) ----
    float* accS = (float*)(smraw + SM_W0);
    if (tid < NB) accS[tid] = 0.0f;
    __syncthreads();
    #pragma unroll
    for (int off = 16; off >= 1; off >>= 1) {
        pA += __shfl_xor_sync(0xffffffffu, pA, off);
        pB += __shfl_xor_sync(0xffffffffu, pB, off);
    }
    if (lane == 0) {
        atomicAdd(&accS[2 * warpT],     pA);
        atomicAdd(&accS[2 * warpT + 1], pB);
    }
    __syncthreads();
    if (tid < NB) out[bbase + tid] = accS[tid];
}

extern "C" void kernel_launch(void* const* d_in, const int* in_sizes, int n_in,
                              void* d_out, int out_size)
{
    const float* x  = (const float*)d_in[0];
    const float* w0 = (const float*)d_in[1];
    const float* b0 = (const float*)d_in[2];
    const float* w1 = (const float*)d_in[3];
    const float* b1 = (const float*)d_in[4];
    const float* w2 = (const float*)d_in[5];
    const float* b2 = (const float*)d_in[6];
    const float* wl = (const float*)d_in[7];
    float* out = (float*)d_out;

    prep_kernel<<<(PREP_TOTAL + 255) / 256, 256>>>(w0, w1, w2);

    cudaFuncSetAttribute(cin_mma_kernel,
                         cudaFuncAttributeMaxDynamicSharedMemorySize, SMEM_BYTES);
    cin_mma_kernel<<<2048 / NB, THREADS, SMEM_BYTES>>>(x, b0, b1, b2, wl, out);
}